// round 1
// baseline (speedup 1.0000x reference)
#include <cuda_runtime.h>
#include <cstdint>

// ---------------- problem constants ----------------
#define D_MODEL 1024
#define SEQ     4096
#define BATCH   8
#define NHEADS  16
#define HDIM    64
#define WIN     128
#define MROWS   (BATCH * SEQ)        // 32768
#define OUT_ELEMS   ((size_t)MROWS * D_MODEL)          // 33554432
#define W_ELEMS     ((size_t)SEQ * 64)                 // 262144

// ---------------- scratch (static device globals; no allocation) ----------------
__device__ float g_kv[(size_t)MROWS * D_MODEL];
__device__ float g_q [(size_t)MROWS * D_MODEL];
__device__ float g_k [(size_t)MROWS * D_MODEL];
__device__ float g_v [(size_t)MROWS * D_MODEL];
__device__ float g_ao[(size_t)MROWS * D_MODEL];

// ---------------- window mean ----------------
// kv[b,s,d] = mean(value[b, max(s-128,0) : min(s+129,S), d])
// thread = (b, d, chunk of 128 s). Sliding sum; coalesced across d.
__global__ void __launch_bounds__(256) window_mean_kernel(
    const float* __restrict__ val, float* __restrict__ kv)
{
    int blk   = blockIdx.x;          // 0..1023
    int dgrp  = blk & 3;
    int chunk = (blk >> 2) & 31;
    int b     = blk >> 7;
    int d     = dgrp * 256 + threadIdx.x;

    const float* base = val + ((size_t)b * SEQ) * D_MODEL + d;
    float*       outp = kv  + ((size_t)b * SEQ) * D_MODEL + d;

    int s0 = chunk * 128;
    int l  = max(s0 - WIN, 0);
    int r  = min(s0 + WIN + 1, SEQ);

    float sum = 0.f;
    for (int j = l; j < r; j++) sum += base[(size_t)j * D_MODEL];

    for (int s = s0; s < s0 + 128; s++) {
        if (s > s0) {
            int rn = s + WIN + 1;
            if (rn <= SEQ) { sum += base[(size_t)(rn - 1) * D_MODEL]; r = rn; }
            int ln = s - WIN;
            if (ln > 0)    { sum -= base[(size_t)(ln - 1) * D_MODEL]; l = ln; }
        }
        outp[(size_t)s * D_MODEL] = sum / (float)(r - l);
    }
}

// ---------------- fp32 GEMM with packed f32x2 FMAs ----------------
// C[m,n] = scale * ( sum_k A[m,k] * W[n,k] + bias[n] )
// A: [M,K] row-major, W: [N,K] row-major. M%128==0, N%128==0, K%16==0.
#define BM 128
#define BN 128
#define BK 16

#define PACK2(d, lo, hi) asm("mov.b64 %0, {%1, %2};" : "=l"(d) : "f"(lo), "f"(hi))
#define UNPACK2(lo, hi, s) asm("mov.b64 {%0, %1}, %2;" : "=f"(lo), "=f"(hi) : "l"(s))
#define FMA2(d, a, b, c) asm("fma.rn.f32x2 %0, %1, %2, %3;" : "=l"(d) : "l"(a), "l"(b), "l"(c))

__global__ void __launch_bounds__(256) gemm_bias_kernel(
    const float* __restrict__ A, const float* __restrict__ W,
    const float* __restrict__ bias, float* __restrict__ C,
    int M, int N, int K, float scale)
{
    __shared__ float As[2][BK][BM];
    __shared__ float Ws[2][BK][BN];

    const int tid = threadIdx.x;
    const int tm  = tid & 15;     // 16 row-groups of 8
    const int tn  = tid >> 4;     // 16 col-groups of 8
    const long bm = blockIdx.y;
    const long bn = blockIdx.x;

    const float* Ag = A + bm * BM * (long)K;
    const float* Wg = W + bn * BN * (long)K;

    // loader mapping: 512 float4 per matrix tile, 2 per thread
    const int r0 = tid >> 2,          c0 = (tid & 3) * 4;
    const int r1 = (tid + 256) >> 2,  c1 = ((tid + 256) & 3) * 4;

    float4 ra0, ra1, rw0, rw1;

    // prologue: load tile 0 -> smem buf 0
    ra0 = *reinterpret_cast<const float4*>(Ag + (long)r0 * K + c0);
    ra1 = *reinterpret_cast<const float4*>(Ag + (long)r1 * K + c1);
    rw0 = *reinterpret_cast<const float4*>(Wg + (long)r0 * K + c0);
    rw1 = *reinterpret_cast<const float4*>(Wg + (long)r1 * K + c1);
    As[0][c0+0][r0]=ra0.x; As[0][c0+1][r0]=ra0.y; As[0][c0+2][r0]=ra0.z; As[0][c0+3][r0]=ra0.w;
    As[0][c1+0][r1]=ra1.x; As[0][c1+1][r1]=ra1.y; As[0][c1+2][r1]=ra1.z; As[0][c1+3][r1]=ra1.w;
    Ws[0][c0+0][r0]=rw0.x; Ws[0][c0+1][r0]=rw0.y; Ws[0][c0+2][r0]=rw0.z; Ws[0][c0+3][r0]=rw0.w;
    Ws[0][c1+0][r1]=rw1.x; Ws[0][c1+1][r1]=rw1.y; Ws[0][c1+2][r1]=rw1.z; Ws[0][c1+3][r1]=rw1.w;
    __syncthreads();

    unsigned long long acc[4][8];
#pragma unroll
    for (int i = 0; i < 4; i++)
#pragma unroll
        for (int j = 0; j < 8; j++) acc[i][j] = 0ULL;

    const int NT = K / BK;
    for (int t = 0; t < NT; t++) {
        const int buf = t & 1;
        if (t + 1 < NT) {
            const float* Ap = Ag + (long)(t + 1) * BK;
            const float* Wp = Wg + (long)(t + 1) * BK;
            ra0 = *reinterpret_cast<const float4*>(Ap + (long)r0 * K + c0);
            ra1 = *reinterpret_cast<const float4*>(Ap + (long)r1 * K + c1);
            rw0 = *reinterpret_cast<const float4*>(Wp + (long)r0 * K + c0);
            rw1 = *reinterpret_cast<const float4*>(Wp + (long)r1 * K + c1);
        }
#pragma unroll
        for (int kk = 0; kk < BK; kk++) {
            float4 a0 = *reinterpret_cast<const float4*>(&As[buf][kk][tm * 8]);
            float4 a1 = *reinterpret_cast<const float4*>(&As[buf][kk][tm * 8 + 4]);
            float4 b0 = *reinterpret_cast<const float4*>(&Ws[buf][kk][tn * 8]);
            float4 b1 = *reinterpret_cast<const float4*>(&Ws[buf][kk][tn * 8 + 4]);
            unsigned long long a2[4];
            PACK2(a2[0], a0.x, a0.y); PACK2(a2[1], a0.z, a0.w);
            PACK2(a2[2], a1.x, a1.y); PACK2(a2[3], a1.z, a1.w);
            float bb[8] = {b0.x, b0.y, b0.z, b0.w, b1.x, b1.y, b1.z, b1.w};
#pragma unroll
            for (int j = 0; j < 8; j++) {
                unsigned long long b2;
                PACK2(b2, bb[j], bb[j]);
#pragma unroll
                for (int i = 0; i < 4; i++) FMA2(acc[i][j], a2[i], b2, acc[i][j]);
            }
        }
        if (t + 1 < NT) {
            const int nb = (t + 1) & 1;
            As[nb][c0+0][r0]=ra0.x; As[nb][c0+1][r0]=ra0.y; As[nb][c0+2][r0]=ra0.z; As[nb][c0+3][r0]=ra0.w;
            As[nb][c1+0][r1]=ra1.x; As[nb][c1+1][r1]=ra1.y; As[nb][c1+2][r1]=ra1.z; As[nb][c1+3][r1]=ra1.w;
            Ws[nb][c0+0][r0]=rw0.x; Ws[nb][c0+1][r0]=rw0.y; Ws[nb][c0+2][r0]=rw0.z; Ws[nb][c0+3][r0]=rw0.w;
            Ws[nb][c1+0][r1]=rw1.x; Ws[nb][c1+1][r1]=rw1.y; Ws[nb][c1+2][r1]=rw1.z; Ws[nb][c1+3][r1]=rw1.w;
        }
        __syncthreads();
    }

    // epilogue: scale*(acc + bias)
    float bcol[8];
#pragma unroll
    for (int j = 0; j < 8; j++) bcol[j] = bias[bn * BN + tn * 8 + j];

#pragma unroll
    for (int i = 0; i < 4; i++) {
        float lo[8], hi[8];
#pragma unroll
        for (int j = 0; j < 8; j++) UNPACK2(lo[j], hi[j], acc[i][j]);
        long m0 = bm * BM + tm * 8 + i * 2;
        float* crow0 = C + m0 * (long)N + bn * BN + tn * 8;
        float* crow1 = crow0 + N;
        float4 o;
        o.x = scale * (lo[0] + bcol[0]); o.y = scale * (lo[1] + bcol[1]);
        o.z = scale * (lo[2] + bcol[2]); o.w = scale * (lo[3] + bcol[3]);
        *reinterpret_cast<float4*>(crow0) = o;
        o.x = scale * (lo[4] + bcol[4]); o.y = scale * (lo[5] + bcol[5]);
        o.z = scale * (lo[6] + bcol[6]); o.w = scale * (lo[7] + bcol[7]);
        *reinterpret_cast<float4*>(crow0 + 4) = o;
        o.x = scale * (hi[0] + bcol[0]); o.y = scale * (hi[1] + bcol[1]);
        o.z = scale * (hi[2] + bcol[2]); o.w = scale * (hi[3] + bcol[3]);
        *reinterpret_cast<float4*>(crow1) = o;
        o.x = scale * (hi[4] + bcol[4]); o.y = scale * (hi[5] + bcol[5]);
        o.z = scale * (hi[6] + bcol[6]); o.w = scale * (hi[7] + bcol[7]);
        *reinterpret_cast<float4*>(crow1 + 4) = o;
    }
}

// ---------------- tiny attention over L=8, per (n, h) ----------------
// One block per n. smem: q[8][1024], k[8][1024], v[8][1024], scores[16][8][8].
#define ATTN_SMEM ((3 * 8 * 1024 + 1024) * 4)   // 102400 bytes

__global__ void __launch_bounds__(256) attention_kernel(
    const float* __restrict__ q, const float* __restrict__ k,
    const float* __restrict__ v, float* __restrict__ attn_out,
    float* __restrict__ weights_out)
{
    extern __shared__ float sm[];
    float* qs  = sm;
    float* ks  = qs + 8 * 1024;
    float* vs  = ks + 8 * 1024;
    float* scr = vs + 8 * 1024;      // [h][l][m]

    const int n = blockIdx.x;
    const int tid = threadIdx.x;

    for (int idx = tid; idx < 8 * 1024; idx += 256) {
        int l = idx >> 10, c = idx & 1023;
        size_t g = ((size_t)(l * SEQ + n)) * D_MODEL + c;
        qs[idx] = q[g];
        ks[idx] = k[g];
        vs[idx] = v[g];
    }
    __syncthreads();

    // scores[h][l][m] = sum_d q[l, h*64+d] * k[m, h*64+d]
    for (int t = tid; t < 1024; t += 256) {
        int h = t >> 6, l = (t >> 3) & 7, m = t & 7;
        const float* qp = qs + l * 1024 + h * HDIM;
        const float* kp = ks + m * 1024 + h * HDIM;
        float s = 0.f;
#pragma unroll
        for (int d = 0; d < HDIM; d++) s += qp[d] * kp[d];
        scr[t] = s;
    }
    __syncthreads();

    // softmax over m, in place
    if (tid < 128) {
        float* row = scr + tid * 8;
        float mx = row[0];
#pragma unroll
        for (int m = 1; m < 8; m++) mx = fmaxf(mx, row[m]);
        float e[8], ssum = 0.f;
#pragma unroll
        for (int m = 0; m < 8; m++) { e[m] = __expf(row[m] - mx); ssum += e[m]; }
        float inv = 1.f / ssum;
#pragma unroll
        for (int m = 0; m < 8; m++) row[m] = e[m] * inv;
    }
    __syncthreads();

    // weights[n][l][m] = mean_h attn[h][l][m]
    if (weights_out != nullptr && tid < 64) {
        float s = 0.f;
#pragma unroll
        for (int h = 0; h < 16; h++) s += scr[h * 64 + tid];
        weights_out[(size_t)n * 64 + tid] = s * (1.f / 16.f);
    }

    // out[l, c] = sum_m attn[h(c)][l][m] * v[m, c]
    for (int t = tid; t < 8 * 1024; t += 256) {
        int l = t >> 10, c = t & 1023;
        int h = c >> 6;
        const float* a = scr + h * 64 + l * 8;
        float s = 0.f;
#pragma unroll
        for (int m = 0; m < 8; m++) s += a[m] * vs[m * 1024 + c];
        attn_out[((size_t)(l * SEQ + n)) * D_MODEL + c] = s;
    }
}

// ---------------- launch ----------------
extern "C" void kernel_launch(void* const* d_in, const int* in_sizes, int n_in,
                              void* d_out, int out_size)
{
    const float* query = (const float*)d_in[0];
    // d_in[1] = key : unused (reference aliasing bug — both pooled tensors are value)
    const float* value = (const float*)d_in[2];
    const float* in_w  = (const float*)d_in[3];   // [3072, 1024]
    const float* in_b  = (const float*)d_in[4];   // [3072]
    const float* out_w = (const float*)d_in[5];   // [1024, 1024]
    const float* out_b = (const float*)d_in[6];   // [1024]

    float* out = (float*)d_out;
    float* wts = ((size_t)out_size >= OUT_ELEMS + W_ELEMS) ? out + OUT_ELEMS : nullptr;

    float *kv, *q, *k, *v, *ao;
    cudaGetSymbolAddress((void**)&kv, g_kv);
    cudaGetSymbolAddress((void**)&q,  g_q);
    cudaGetSymbolAddress((void**)&k,  g_k);
    cudaGetSymbolAddress((void**)&v,  g_v);
    cudaGetSymbolAddress((void**)&ao, g_ao);

    cudaFuncSetAttribute(attention_kernel,
                         cudaFuncAttributeMaxDynamicSharedMemorySize, ATTN_SMEM);

    // 1. kv = window_mean(value)
    window_mean_kernel<<<BATCH * 32 * 4, 256>>>(value, kv);

    // 2. q = (query @ Wq^T + bq) / 8
    dim3 gg(D_MODEL / BN, MROWS / BM);
    gemm_bias_kernel<<<gg, 256>>>(query, in_w, in_b, q,
                                  MROWS, D_MODEL, D_MODEL, 0.125f);
    // 3. k = kv @ Wk^T + bk
    gemm_bias_kernel<<<gg, 256>>>(kv, in_w + (size_t)D_MODEL * D_MODEL,
                                  in_b + D_MODEL, k,
                                  MROWS, D_MODEL, D_MODEL, 1.0f);
    // 4. v = kv @ Wv^T + bv
    gemm_bias_kernel<<<gg, 256>>>(kv, in_w + 2 * (size_t)D_MODEL * D_MODEL,
                                  in_b + 2 * D_MODEL, v,
                                  MROWS, D_MODEL, D_MODEL, 1.0f);

    // 5. attention per n (L=8 tokens), also emits averaged weights
    attention_kernel<<<SEQ, 256, ATTN_SMEM>>>(q, k, v, ao, wts);

    // 6. out = ao @ Wo^T + bo  -> d_out
    gemm_bias_kernel<<<gg, 256>>>(ao, out_w, out_b, out,
                                  MROWS, D_MODEL, D_MODEL, 1.0f);
}

// round 3
// speedup vs baseline: 2.8721x; 2.8721x over previous
#include <cuda_runtime.h>
#include <cuda_bf16.h>
#include <cstdint>

// ---------------- problem constants ----------------
#define D_MODEL 1024
#define SEQ     4096
#define BATCH   8
#define HDIM    64
#define WIN     128
#define MROWS   (BATCH * SEQ)                          // 32768
#define OUT_ELEMS ((size_t)MROWS * D_MODEL)            // 33554432
#define W_ELEMS   ((size_t)SEQ * 64)                   // 262144

// ---------------- scratch (static device globals) ----------------
__device__ float g_kv[OUT_ELEMS];
__device__ float g_q [OUT_ELEMS];
__device__ float g_k [OUT_ELEMS];
__device__ float g_v [OUT_ELEMS];
__device__ float g_ao[OUT_ELEMS];
__device__ __nv_bfloat16 g_Ah[OUT_ELEMS];
__device__ __nv_bfloat16 g_Al[OUT_ELEMS];
__device__ __nv_bfloat16 g_Wh[4u * 1024u * 1024u];
__device__ __nv_bfloat16 g_Wl[4u * 1024u * 1024u];

// ---------------- PTX helpers (sm_90 baseline features only) ----------------
__device__ __forceinline__ uint32_t smem_u32(const void* p) {
    uint32_t a;
    asm("{ .reg .u64 t; cvta.to.shared.u64 t, %1; cvt.u32.u64 %0, t; }" : "=r"(a) : "l"(p));
    return a;
}
__device__ __forceinline__ void mbar_init(uint32_t m, uint32_t cnt) {
    asm volatile("mbarrier.init.shared.b64 [%0], %1;" :: "r"(m), "r"(cnt) : "memory");
}
__device__ __forceinline__ void mbar_expect_tx(uint32_t m, uint32_t bytes) {
    asm volatile("mbarrier.arrive.expect_tx.shared.b64 _, [%0], %1;" :: "r"(m), "r"(bytes) : "memory");
}
__device__ __forceinline__ void mbar_arrive(uint32_t m) {
    asm volatile("mbarrier.arrive.shared.b64 _, [%0];" :: "r"(m) : "memory");
}
__device__ __forceinline__ void mbar_wait(uint32_t m, uint32_t parity) {
    asm volatile(
        "{\n\t.reg .pred P;\n\t"
        "WL_%=:\n\t"
        "mbarrier.try_wait.parity.acquire.cta.shared::cta.b64 P, [%0], %1, 0x989680;\n\t"
        "@P bra.uni WD_%=;\n\t"
        "bra.uni WL_%=;\n\t"
        "WD_%=:\n\t}"
        :: "r"(m), "r"(parity) : "memory");
}
__device__ __forceinline__ void bulk_g2s(uint32_t dst, const void* src, uint32_t bytes, uint32_t mbar) {
    asm volatile(
        "cp.async.bulk.shared::cluster.global.mbarrier::complete_tx::bytes [%0], [%1], %2, [%3];"
        :: "r"(dst), "l"(src), "r"(bytes), "r"(mbar) : "memory");
}

#define LDSM4(r, a) \
    asm volatile("ldmatrix.sync.aligned.m8n8.x4.shared.b16 {%0,%1,%2,%3}, [%4];" \
        : "=r"((r)[0]), "=r"((r)[1]), "=r"((r)[2]), "=r"((r)[3]) : "r"(a))

#define MMA16816(c, a, b0, b1) \
    asm volatile("mma.sync.aligned.m16n8k16.row.col.f32.bf16.bf16.f32 " \
        "{%0,%1,%2,%3}, {%4,%5,%6,%7}, {%8,%9}, {%0,%1,%2,%3};" \
        : "+f"((c)[0]), "+f"((c)[1]), "+f"((c)[2]), "+f"((c)[3]) \
        : "r"((a)[0]), "r"((a)[1]), "r"((a)[2]), "r"((a)[3]), "r"(b0), "r"(b1))

__host__ __device__ __forceinline__ uint32_t swz128(uint32_t o) { return o ^ ((o >> 3) & 0x70); }

// ---------------- window mean ----------------
__global__ void __launch_bounds__(256) window_mean_kernel(
    const float* __restrict__ val, float* __restrict__ kv)
{
    int blk   = blockIdx.x;
    int dgrp  = blk & 3;
    int chunk = (blk >> 2) & 31;
    int b     = blk >> 7;
    int d     = dgrp * 256 + threadIdx.x;

    const float* base = val + ((size_t)b * SEQ) * D_MODEL + d;
    float*       outp = kv  + ((size_t)b * SEQ) * D_MODEL + d;

    int s0 = chunk * 128;
    int l  = max(s0 - WIN, 0);
    int r  = min(s0 + WIN + 1, SEQ);

    float sum = 0.f;
    for (int j = l; j < r; j++) sum += base[(size_t)j * D_MODEL];

    for (int s = s0; s < s0 + 128; s++) {
        if (s > s0) {
            int rn = s + WIN + 1;
            if (rn <= SEQ) { sum += base[(size_t)(rn - 1) * D_MODEL]; r = rn; }
            int ln = s - WIN;
            if (ln > 0)    { sum -= base[(size_t)(ln - 1) * D_MODEL]; l = ln; }
        }
        outp[(size_t)s * D_MODEL] = sum / (float)(r - l);
    }
}

// ---------------- fp32 -> (bf16 hi, bf16 lo), 128-row tiles, pre-SW128-swizzled ----------------
// Tile (rowblk mb, kchunk kc) of [128 rows][64 bf16] at byte offset (mb*16+kc)*16384.
__global__ void __launch_bounds__(256) convert_split_kernel(
    const float* __restrict__ x, char* __restrict__ hi, char* __restrict__ lo)
{
    size_t idx = (size_t)blockIdx.x * 256 + threadIdx.x;   // one per 8 elements
    int m = (int)(idx >> 7);
    int k = (int)(idx & 127) << 3;

    const float4* p = reinterpret_cast<const float4*>(x + (size_t)m * 1024 + k);
    float4 f0 = p[0], f1 = p[1];
    float f[8] = {f0.x, f0.y, f0.z, f0.w, f1.x, f1.y, f1.z, f1.w};

    uint32_t hp[4], lp[4];
#pragma unroll
    for (int i = 0; i < 4; i++) {
        __nv_bfloat16 h0 = __float2bfloat16_rn(f[2*i]);
        __nv_bfloat16 h1 = __float2bfloat16_rn(f[2*i+1]);
        __nv_bfloat16 l0 = __float2bfloat16_rn(f[2*i]   - __bfloat162float(h0));
        __nv_bfloat16 l1 = __float2bfloat16_rn(f[2*i+1] - __bfloat162float(h1));
        unsigned short u0 = *reinterpret_cast<unsigned short*>(&h0);
        unsigned short u1 = *reinterpret_cast<unsigned short*>(&h1);
        unsigned short w0 = *reinterpret_cast<unsigned short*>(&l0);
        unsigned short w1 = *reinterpret_cast<unsigned short*>(&l1);
        hp[i] = (uint32_t)u0 | ((uint32_t)u1 << 16);
        lp[i] = (uint32_t)w0 | ((uint32_t)w1 << 16);
    }

    int mb  = m >> 7;
    int row = m & 127;
    int kc  = k >> 6;
    int col = k & 63;
    uint32_t off = swz128((uint32_t)(row * 128 + col * 2));
    size_t tb = ((size_t)mb * 16 + kc) * 16384;

    *reinterpret_cast<uint4*>(hi + tb + off) = make_uint4(hp[0], hp[1], hp[2], hp[3]);
    *reinterpret_cast<uint4*>(lo + tb + off) = make_uint4(lp[0], lp[1], lp[2], lp[3]);
}

// ---------------- mma.sync GEMM: C[m,n] = scale*(sum_k A[m,k]*W[n,k] + bias[n]) ----------------
// A,W split (hi,lo), blocked [blk][16][128][64] pre-swizzled. CTA 128x128, 8 warps (2Mx4N),
// warp tile 64x32, K-chunk 64, 3-stage cp.async.bulk pipeline, 3-term bf16 split.
#define STAGE_BYTES 65536
#define NSTAGE 3
#define GEMM_SMEM (NSTAGE * STAGE_BYTES + 1024)

__global__ void __launch_bounds__(256, 1) gemm_mma_kernel(
    const __nv_bfloat16* __restrict__ Ah, const __nv_bfloat16* __restrict__ Al,
    const __nv_bfloat16* __restrict__ Wh, const __nv_bfloat16* __restrict__ Wl,
    const float* __restrict__ bias, float* __restrict__ C, float scale)
{
    extern __shared__ char dsm[];
    __shared__ __align__(8) uint64_t bars[2 * NSTAGE];   // full[3], empty[3]

    const int tid  = threadIdx.x;
    const int lane = tid & 31;
    const int w    = tid >> 5;
    const int wm   = w & 1;          // 0..1  (M groups of 64)
    const int wn   = w >> 1;         // 0..3  (N groups of 32)

    const uint32_t smraw = smem_u32(dsm);
    const uint32_t base  = (smraw + 1023u) & ~1023u;

    if (tid == 0) {
        for (int i = 0; i < NSTAGE; i++) {
            mbar_init(smem_u32(&bars[i]), 1);                // full: tx-based
            mbar_init(smem_u32(&bars[NSTAGE + i]), 256);     // empty: all threads
        }
        asm volatile("fence.proxy.async.shared::cta;" ::: "memory");
    }
    __syncthreads();

    uint32_t bfull[NSTAGE], bempty[NSTAGE];
#pragma unroll
    for (int i = 0; i < NSTAGE; i++) {
        bfull[i]  = smem_u32(&bars[i]);
        bempty[i] = smem_u32(&bars[NSTAGE + i]);
    }

    const int nb = blockIdx.x;       // N block (8)
    const int mb = blockIdx.y;       // M block (256)
    const char* ah = (const char*)Ah + (size_t)mb * 16 * 16384;
    const char* al = (const char*)Al + (size_t)mb * 16 * 16384;
    const char* wh = (const char*)Wh + (size_t)nb * 16 * 16384;
    const char* wl = (const char*)Wl + (size_t)nb * 16 * 16384;

    // prologue: issue chunks 0,1 into stages 0,1
    if (tid == 0) {
#pragma unroll
        for (int p = 0; p < 2; p++) {
            const uint32_t st = base + p * STAGE_BYTES;
            mbar_expect_tx(bfull[p], STAGE_BYTES);
            bulk_g2s(st,         ah + (size_t)p * 16384, 16384, bfull[p]);
            bulk_g2s(st + 16384, al + (size_t)p * 16384, 16384, bfull[p]);
            bulk_g2s(st + 32768, wh + (size_t)p * 16384, 16384, bfull[p]);
            bulk_g2s(st + 49152, wl + (size_t)p * 16384, 16384, bfull[p]);
        }
    }

    // per-thread ldmatrix address components (SW128: addr = row*128 + (colbytes ^ ((row&7)<<4)))
    const int r3 = lane & 7;
    const uint32_t xr = (uint32_t)(r3 << 4);
    const int arow = wm * 64 + r3 + ((lane >> 3) & 1) * 8;   // + mi*16
    const uint32_t akh = (uint32_t)((lane >> 4) << 4);       // A k-half: 0 or 16 bytes
    const int brow = wn * 32 + (lane >> 4) * 8 + r3;         // + j*16
    const uint32_t bkh = (uint32_t)(((lane >> 3) & 1) << 4); // B k-half

    float c[4][4][4];
#pragma unroll
    for (int mi = 0; mi < 4; mi++)
#pragma unroll
        for (int ni = 0; ni < 4; ni++)
#pragma unroll
            for (int j = 0; j < 4; j++) c[mi][ni][j] = 0.f;

    for (int t = 0; t < 16; t++) {
        const int s = t % 3;
        if (tid == 0 && t + 2 < 16) {
            const int s2 = (t + 2) % 3;
            mbar_wait(bempty[s2], (uint32_t)((((t + 2) / 3) & 1) ^ 1));
            mbar_expect_tx(bfull[s2], STAGE_BYTES);
            const uint32_t st = base + s2 * STAGE_BYTES;
            bulk_g2s(st,         ah + (size_t)(t + 2) * 16384, 16384, bfull[s2]);
            bulk_g2s(st + 16384, al + (size_t)(t + 2) * 16384, 16384, bfull[s2]);
            bulk_g2s(st + 32768, wh + (size_t)(t + 2) * 16384, 16384, bfull[s2]);
            bulk_g2s(st + 49152, wl + (size_t)(t + 2) * 16384, 16384, bfull[s2]);
        }
        mbar_wait(bfull[s], (uint32_t)((t / 3) & 1));

        const uint32_t st  = base + s * STAGE_BYTES;
        const uint32_t tAh = st, tAl = st + 16384, tWh = st + 32768, tWl = st + 49152;

#pragma unroll
        for (int ks = 0; ks < 4; ks++) {
            const uint32_t offA = ((uint32_t)(ks * 32) + akh) ^ xr;
            const uint32_t offB = ((uint32_t)(ks * 32) + bkh) ^ xr;

            uint32_t ahf[4][4], alf[4][4], bhf[2][4], blf[2][4];
#pragma unroll
            for (int mi = 0; mi < 4; mi++) {
                const uint32_t ra = (uint32_t)((arow + mi * 16) * 128);
                LDSM4(ahf[mi], tAh + ra + offA);
                LDSM4(alf[mi], tAl + ra + offA);
            }
#pragma unroll
            for (int j = 0; j < 2; j++) {
                const uint32_t rb = (uint32_t)((brow + j * 16) * 128);
                LDSM4(bhf[j], tWh + rb + offB);
                LDSM4(blf[j], tWl + rb + offB);
            }
#pragma unroll
            for (int mi = 0; mi < 4; mi++) {
#pragma unroll
                for (int ni = 0; ni < 4; ni++) {
                    const uint32_t* bh = &bhf[ni >> 1][(ni & 1) * 2];
                    const uint32_t* bl = &blf[ni >> 1][(ni & 1) * 2];
                    MMA16816(c[mi][ni], ahf[mi], bh[0], bh[1]);
                    MMA16816(c[mi][ni], ahf[mi], bl[0], bl[1]);
                    MMA16816(c[mi][ni], alf[mi], bh[0], bh[1]);
                }
            }
        }
        mbar_arrive(bempty[s]);
    }

    // epilogue: regs -> gmem with bias + scale
    const int g   = lane >> 2;
    const int tig = lane & 3;
    const long m_base = (long)mb * 128 + wm * 64;
    const long n_base = (long)nb * 128 + wn * 32;
#pragma unroll
    for (int ni = 0; ni < 4; ni++) {
        const long col0 = n_base + ni * 8 + tig * 2;
        const float b0 = bias[col0], b1 = bias[col0 + 1];
#pragma unroll
        for (int mi = 0; mi < 4; mi++) {
            const long r0 = m_base + mi * 16 + g;
            float2 o0, o1;
            o0.x = scale * (c[mi][ni][0] + b0);
            o0.y = scale * (c[mi][ni][1] + b1);
            o1.x = scale * (c[mi][ni][2] + b0);
            o1.y = scale * (c[mi][ni][3] + b1);
            *reinterpret_cast<float2*>(C + r0 * D_MODEL + col0)       = o0;
            *reinterpret_cast<float2*>(C + (r0 + 8) * D_MODEL + col0) = o1;
        }
    }
}

// ---------------- tiny attention over L=8, per (n, h) ----------------
#define ATTN_SMEM ((3 * 8 * 1024 + 1024) * 4)   // 102400 bytes

__global__ void __launch_bounds__(256) attention_kernel(
    const float* __restrict__ q, const float* __restrict__ k,
    const float* __restrict__ v, float* __restrict__ attn_out,
    float* __restrict__ weights_out)
{
    extern __shared__ float sm[];
    float* qs  = sm;
    float* ks  = qs + 8 * 1024;
    float* vs  = ks + 8 * 1024;
    float* scr = vs + 8 * 1024;

    const int n = blockIdx.x;
    const int tid = threadIdx.x;

    for (int idx = tid; idx < 8 * 1024; idx += 256) {
        int l = idx >> 10, c = idx & 1023;
        size_t g = ((size_t)(l * SEQ + n)) * D_MODEL + c;
        qs[idx] = q[g];
        ks[idx] = k[g];
        vs[idx] = v[g];
    }
    __syncthreads();

    for (int t = tid; t < 1024; t += 256) {
        int h = t >> 6, l = (t >> 3) & 7, m = t & 7;
        const float* qp = qs + l * 1024 + h * HDIM;
        const float* kp = ks + m * 1024 + h * HDIM;
        float s = 0.f;
#pragma unroll
        for (int d = 0; d < HDIM; d++) s += qp[d] * kp[d];
        scr[t] = s;
    }
    __syncthreads();

    if (tid < 128) {
        float* rowp = scr + tid * 8;
        float mx = rowp[0];
#pragma unroll
        for (int m = 1; m < 8; m++) mx = fmaxf(mx, rowp[m]);
        float e[8], ssum = 0.f;
#pragma unroll
        for (int m = 0; m < 8; m++) { e[m] = __expf(rowp[m] - mx); ssum += e[m]; }
        float inv = 1.f / ssum;
#pragma unroll
        for (int m = 0; m < 8; m++) rowp[m] = e[m] * inv;
    }
    __syncthreads();

    if (weights_out != nullptr && tid < 64) {
        float s = 0.f;
#pragma unroll
        for (int h = 0; h < 16; h++) s += scr[h * 64 + tid];
        weights_out[(size_t)n * 64 + tid] = s * (1.f / 16.f);
    }

    for (int t = tid; t < 8 * 1024; t += 256) {
        int l = t >> 10, c = t & 1023;
        int h = c >> 6;
        const float* a = scr + h * 64 + l * 8;
        float s = 0.f;
#pragma unroll
        for (int m = 0; m < 8; m++) s += a[m] * vs[m * 1024 + c];
        attn_out[((size_t)(l * SEQ + n)) * D_MODEL + c] = s;
    }
}

// ---------------- launch ----------------
extern "C" void kernel_launch(void* const* d_in, const int* in_sizes, int n_in,
                              void* d_out, int out_size)
{
    const float* query = (const float*)d_in[0];
    // d_in[1] = key : unused (reference aliasing bug — both pooled tensors are value)
    const float* value = (const float*)d_in[2];
    const float* in_w  = (const float*)d_in[3];
    const float* in_b  = (const float*)d_in[4];
    const float* out_w = (const float*)d_in[5];
    const float* out_b = (const float*)d_in[6];

    float* out = (float*)d_out;
    float* wts = ((size_t)out_size >= OUT_ELEMS + W_ELEMS) ? out + OUT_ELEMS : nullptr;

    float *kv, *q, *k, *v, *ao;
    __nv_bfloat16 *Ah, *Al, *Wh, *Wl;
    cudaGetSymbolAddress((void**)&kv, g_kv);
    cudaGetSymbolAddress((void**)&q,  g_q);
    cudaGetSymbolAddress((void**)&k,  g_k);
    cudaGetSymbolAddress((void**)&v,  g_v);
    cudaGetSymbolAddress((void**)&ao, g_ao);
    cudaGetSymbolAddress((void**)&Ah, g_Ah);
    cudaGetSymbolAddress((void**)&Al, g_Al);
    cudaGetSymbolAddress((void**)&Wh, g_Wh);
    cudaGetSymbolAddress((void**)&Wl, g_Wl);

    cudaFuncSetAttribute(gemm_mma_kernel,
                         cudaFuncAttributeMaxDynamicSharedMemorySize, GEMM_SMEM);
    cudaFuncSetAttribute(attention_kernel,
                         cudaFuncAttributeMaxDynamicSharedMemorySize, ATTN_SMEM);

    const size_t WSTRIDE = 1024u * 1024u;   // elems per weight matrix (blocked layout)
    dim3 gg(8, 256);                        // N/128 x M/128

    // 1. kv = window_mean(value)
    window_mean_kernel<<<BATCH * 32 * 4, 256>>>(value, kv);

    // 2. convert weights: in_proj (3072 rows) + out_proj (1024 rows)
    convert_split_kernel<<<(3072 * 128) / 256, 256>>>(in_w, (char*)Wh, (char*)Wl);
    convert_split_kernel<<<(1024 * 128) / 256, 256>>>(out_w, (char*)(Wh + 3 * WSTRIDE),
                                                      (char*)(Wl + 3 * WSTRIDE));

    // 3. q = (query @ Wq^T + bq) / 8
    convert_split_kernel<<<(MROWS * 128) / 256, 256>>>(query, (char*)Ah, (char*)Al);
    gemm_mma_kernel<<<gg, 256, GEMM_SMEM>>>(Ah, Al, Wh, Wl, in_b, q, 0.125f);

    // 4. k = kv @ Wk^T + bk ;  v = kv @ Wv^T + bv
    convert_split_kernel<<<(MROWS * 128) / 256, 256>>>(kv, (char*)Ah, (char*)Al);
    gemm_mma_kernel<<<gg, 256, GEMM_SMEM>>>(Ah, Al, Wh + WSTRIDE,     Wl + WSTRIDE,
                                            in_b + 1024, k, 1.0f);
    gemm_mma_kernel<<<gg, 256, GEMM_SMEM>>>(Ah, Al, Wh + 2 * WSTRIDE, Wl + 2 * WSTRIDE,
                                            in_b + 2048, v, 1.0f);

    // 5. attention per n (L=8 tokens) + averaged weights
    attention_kernel<<<SEQ, 256, ATTN_SMEM>>>(q, k, v, ao, wts);

    // 6. out = ao @ Wo^T + bo -> d_out
    convert_split_kernel<<<(MROWS * 128) / 256, 256>>>(ao, (char*)Ah, (char*)Al);
    gemm_mma_kernel<<<gg, 256, GEMM_SMEM>>>(Ah, Al, Wh + 3 * WSTRIDE, Wl + 3 * WSTRIDE,
                                            out_b, out, 1.0f);
}

// round 6
// speedup vs baseline: 3.1952x; 1.1125x over previous
#include <cuda_runtime.h>
#include <cuda_bf16.h>
#include <cstdint>

// ---------------- problem constants ----------------
#define D_MODEL 1024
#define SEQ     4096
#define BATCH   8
#define HDIM    64
#define WIN     128
#define MROWS   (BATCH * SEQ)                          // 32768
#define OUT_ELEMS ((size_t)MROWS * D_MODEL)            // 33554432
#define W_ELEMS   ((size_t)SEQ * 64)                   // 262144

// ---------------- scratch (static device globals) ----------------
__device__ float g_q [OUT_ELEMS];
__device__ float g_k [OUT_ELEMS];
__device__ float g_v [OUT_ELEMS];
__device__ __nv_bfloat16 g_Ah[OUT_ELEMS];   // kv split
__device__ __nv_bfloat16 g_Al[OUT_ELEMS];
__device__ __nv_bfloat16 g_Qh[OUT_ELEMS];   // query split, then ao split
__device__ __nv_bfloat16 g_Ql[OUT_ELEMS];
__device__ __nv_bfloat16 g_Wh[4u * 1024u * 1024u];   // slots: 0=Wq 1=Wk 2=Wv 3=Wo
__device__ __nv_bfloat16 g_Wl[4u * 1024u * 1024u];

// ---------------- PTX helpers (sm_90 baseline features only) ----------------
__device__ __forceinline__ uint32_t smem_u32(const void* p) {
    uint32_t a;
    asm("{ .reg .u64 t; cvta.to.shared.u64 t, %1; cvt.u32.u64 %0, t; }" : "=r"(a) : "l"(p));
    return a;
}
__device__ __forceinline__ void mbar_init(uint32_t m, uint32_t cnt) {
    asm volatile("mbarrier.init.shared.b64 [%0], %1;" :: "r"(m), "r"(cnt) : "memory");
}
__device__ __forceinline__ void mbar_expect_tx(uint32_t m, uint32_t bytes) {
    asm volatile("mbarrier.arrive.expect_tx.shared.b64 _, [%0], %1;" :: "r"(m), "r"(bytes) : "memory");
}
__device__ __forceinline__ void mbar_arrive(uint32_t m) {
    asm volatile("mbarrier.arrive.shared.b64 _, [%0];" :: "r"(m) : "memory");
}
__device__ __forceinline__ void mbar_wait(uint32_t m, uint32_t parity) {
    asm volatile(
        "{\n\t.reg .pred P;\n\t"
        "WL_%=:\n\t"
        "mbarrier.try_wait.parity.acquire.cta.shared::cta.b64 P, [%0], %1, 0x989680;\n\t"
        "@P bra.uni WD_%=;\n\t"
        "bra.uni WL_%=;\n\t"
        "WD_%=:\n\t}"
        :: "r"(m), "r"(parity) : "memory");
}
__device__ __forceinline__ void bulk_g2s(uint32_t dst, const void* src, uint32_t bytes, uint32_t mbar) {
    asm volatile(
        "cp.async.bulk.shared::cluster.global.mbarrier::complete_tx::bytes [%0], [%1], %2, [%3];"
        :: "r"(dst), "l"(src), "r"(bytes), "r"(mbar) : "memory");
}

#define LDSM4(r, a) \
    asm volatile("ldmatrix.sync.aligned.m8n8.x4.shared.b16 {%0,%1,%2,%3}, [%4];" \
        : "=r"((r)[0]), "=r"((r)[1]), "=r"((r)[2]), "=r"((r)[3]) : "r"(a))

#define MMA16816(c, a, b0, b1) \
    asm volatile("mma.sync.aligned.m16n8k16.row.col.f32.bf16.bf16.f32 " \
        "{%0,%1,%2,%3}, {%4,%5,%6,%7}, {%8,%9}, {%0,%1,%2,%3};" \
        : "+f"((c)[0]), "+f"((c)[1]), "+f"((c)[2]), "+f"((c)[3]) \
        : "r"((a)[0]), "r"((a)[1]), "r"((a)[2]), "r"((a)[3]), "r"(b0), "r"(b1))

__host__ __device__ __forceinline__ uint32_t swz128(uint32_t o) { return o ^ ((o >> 3) & 0x70); }

__device__ __forceinline__ uint32_t split_pack_hi(float f0, float f1,
                                                  float& r0, float& r1) {
    __nv_bfloat16 h0 = __float2bfloat16_rn(f0);
    __nv_bfloat16 h1 = __float2bfloat16_rn(f1);
    r0 = f0 - __bfloat162float(h0);
    r1 = f1 - __bfloat162float(h1);
    unsigned short u0 = *reinterpret_cast<unsigned short*>(&h0);
    unsigned short u1 = *reinterpret_cast<unsigned short*>(&h1);
    return (uint32_t)u0 | ((uint32_t)u1 << 16);
}
__device__ __forceinline__ uint32_t pack_bf16(float f0, float f1) {
    __nv_bfloat16 h0 = __float2bfloat16_rn(f0);
    __nv_bfloat16 h1 = __float2bfloat16_rn(f1);
    unsigned short u0 = *reinterpret_cast<unsigned short*>(&h0);
    unsigned short u1 = *reinterpret_cast<unsigned short*>(&h1);
    return (uint32_t)u0 | ((uint32_t)u1 << 16);
}

// ---------------- window mean fused with bf16 split ----------------
// Writes split(kv) directly into blocked/pre-swizzled A tiles (no fp32 kv).
__global__ void __launch_bounds__(512) window_mean_split_kernel(
    const float* __restrict__ val, char* __restrict__ hi, char* __restrict__ lo)
{
    int blk   = blockIdx.x;
    int chunk = blk & 31;
    int b     = blk >> 5;
    int d     = threadIdx.x * 2;

    const float2* base = reinterpret_cast<const float2*>(
        val + ((size_t)b * SEQ) * D_MODEL + d);

    int s0 = chunk * 128;
    int l  = max(s0 - WIN, 0);
    int r  = min(s0 + WIN + 1, SEQ);

    float sx = 0.f, sy = 0.f;
    for (int j = l; j < r; j++) {
        float2 t = base[(size_t)j * (D_MODEL / 2)];
        sx += t.x; sy += t.y;
    }

    const int kc  = d >> 6;
    const int col = d & 63;
    for (int s = s0; s < s0 + 128; s++) {
        if (s > s0) {
            int rn = s + WIN + 1;
            if (rn <= SEQ) {
                float2 t = base[(size_t)(rn - 1) * (D_MODEL / 2)];
                sx += t.x; sy += t.y; r = rn;
            }
            int ln = s - WIN;
            if (ln > 0) {
                float2 t = base[(size_t)(ln - 1) * (D_MODEL / 2)];
                sx -= t.x; sy -= t.y; l = ln;
            }
        }
        float inv = 1.f / (float)(r - l);
        float m0 = sx * inv, m1 = sy * inv;
        float r0, r1;
        uint32_t hp = split_pack_hi(m0, m1, r0, r1);
        uint32_t lp = pack_bf16(r0, r1);

        int m   = b * SEQ + s;
        int mb  = m >> 7, row = m & 127;
        uint32_t off = swz128((uint32_t)(row * 128 + col * 2));
        size_t tb = ((size_t)mb * 16 + kc) * 16384;
        *reinterpret_cast<uint32_t*>(hi + tb + off) = hp;
        *reinterpret_cast<uint32_t*>(lo + tb + off) = lp;
    }
}

// ---------------- fp32 -> (bf16 hi, bf16 lo), 128-row tiles, pre-SW128-swizzled ----------------
__global__ void __launch_bounds__(256) convert_split_kernel(
    const float* __restrict__ x, char* __restrict__ hi, char* __restrict__ lo)
{
    size_t idx = (size_t)blockIdx.x * 256 + threadIdx.x;   // one per 8 elements
    int m = (int)(idx >> 7);
    int k = (int)(idx & 127) << 3;

    const float4* p = reinterpret_cast<const float4*>(x + (size_t)m * 1024 + k);
    float4 f0 = p[0], f1 = p[1];
    float f[8] = {f0.x, f0.y, f0.z, f0.w, f1.x, f1.y, f1.z, f1.w};

    uint32_t hp[4], lp[4];
#pragma unroll
    for (int i = 0; i < 4; i++) {
        float r0, r1;
        hp[i] = split_pack_hi(f[2*i], f[2*i+1], r0, r1);
        lp[i] = pack_bf16(r0, r1);
    }

    int mb  = m >> 7;
    int row = m & 127;
    int kc  = k >> 6;
    int col = k & 63;
    uint32_t off = swz128((uint32_t)(row * 128 + col * 2));
    size_t tb = ((size_t)mb * 16 + kc) * 16384;

    *reinterpret_cast<uint4*>(hi + tb + off) = make_uint4(hp[0], hp[1], hp[2], hp[3]);
    *reinterpret_cast<uint4*>(lo + tb + off) = make_uint4(lp[0], lp[1], lp[2], lp[3]);
}

// ---------------- mma.sync GEMM: C[m,n] = scale*(sum_k A[m,k]*W[n,k] + bias[n]) ----------------
#define STAGE_BYTES 65536
#define NSTAGE 3
#define GEMM_SMEM (NSTAGE * STAGE_BYTES + 1024)

__global__ void __launch_bounds__(256, 1) gemm_mma_kernel(
    const __nv_bfloat16* __restrict__ Ah, const __nv_bfloat16* __restrict__ Al,
    const __nv_bfloat16* __restrict__ Wh, const __nv_bfloat16* __restrict__ Wl,
    const float* __restrict__ bias, float* __restrict__ C, float scale)
{
    extern __shared__ char dsm[];
    __shared__ __align__(8) uint64_t bars[2 * NSTAGE];

    const int tid  = threadIdx.x;
    const int lane = tid & 31;
    const int w    = tid >> 5;
    const int wm   = w & 1;
    const int wn   = w >> 1;

    const uint32_t smraw = smem_u32(dsm);
    const uint32_t base  = (smraw + 1023u) & ~1023u;

    if (tid == 0) {
        for (int i = 0; i < NSTAGE; i++) {
            mbar_init(smem_u32(&bars[i]), 1);
            mbar_init(smem_u32(&bars[NSTAGE + i]), 256);
        }
        asm volatile("fence.proxy.async.shared::cta;" ::: "memory");
    }
    __syncthreads();

    uint32_t bfull[NSTAGE], bempty[NSTAGE];
#pragma unroll
    for (int i = 0; i < NSTAGE; i++) {
        bfull[i]  = smem_u32(&bars[i]);
        bempty[i] = smem_u32(&bars[NSTAGE + i]);
    }

    const int nb = blockIdx.x;
    const int mb = blockIdx.y;
    const char* ah = (const char*)Ah + (size_t)mb * 16 * 16384;
    const char* al = (const char*)Al + (size_t)mb * 16 * 16384;
    const char* wh = (const char*)Wh + (size_t)nb * 16 * 16384;
    const char* wl = (const char*)Wl + (size_t)nb * 16 * 16384;

    if (tid == 0) {
#pragma unroll
        for (int p = 0; p < 2; p++) {
            const uint32_t st = base + p * STAGE_BYTES;
            mbar_expect_tx(bfull[p], STAGE_BYTES);
            bulk_g2s(st,         ah + (size_t)p * 16384, 16384, bfull[p]);
            bulk_g2s(st + 16384, al + (size_t)p * 16384, 16384, bfull[p]);
            bulk_g2s(st + 32768, wh + (size_t)p * 16384, 16384, bfull[p]);
            bulk_g2s(st + 49152, wl + (size_t)p * 16384, 16384, bfull[p]);
        }
    }

    const int r3 = lane & 7;
    const uint32_t xr = (uint32_t)(r3 << 4);
    const int arow = wm * 64 + r3 + ((lane >> 3) & 1) * 8;
    const uint32_t akh = (uint32_t)((lane >> 4) << 4);
    const int brow = wn * 32 + (lane >> 4) * 8 + r3;
    const uint32_t bkh = (uint32_t)(((lane >> 3) & 1) << 4);

    float c[4][4][4];
#pragma unroll
    for (int mi = 0; mi < 4; mi++)
#pragma unroll
        for (int ni = 0; ni < 4; ni++)
#pragma unroll
            for (int j = 0; j < 4; j++) c[mi][ni][j] = 0.f;

    for (int t = 0; t < 16; t++) {
        const int s = t % 3;
        if (tid == 0 && t + 2 < 16) {
            const int s2 = (t + 2) % 3;
            mbar_wait(bempty[s2], (uint32_t)((((t + 2) / 3) & 1) ^ 1));
            mbar_expect_tx(bfull[s2], STAGE_BYTES);
            const uint32_t st = base + s2 * STAGE_BYTES;
            bulk_g2s(st,         ah + (size_t)(t + 2) * 16384, 16384, bfull[s2]);
            bulk_g2s(st + 16384, al + (size_t)(t + 2) * 16384, 16384, bfull[s2]);
            bulk_g2s(st + 32768, wh + (size_t)(t + 2) * 16384, 16384, bfull[s2]);
            bulk_g2s(st + 49152, wl + (size_t)(t + 2) * 16384, 16384, bfull[s2]);
        }
        mbar_wait(bfull[s], (uint32_t)((t / 3) & 1));

        const uint32_t st  = base + s * STAGE_BYTES;
        const uint32_t tAh = st, tAl = st + 16384, tWh = st + 32768, tWl = st + 49152;

#pragma unroll
        for (int ks = 0; ks < 4; ks++) {
            const uint32_t offA = ((uint32_t)(ks * 32) + akh) ^ xr;
            const uint32_t offB = ((uint32_t)(ks * 32) + bkh) ^ xr;

            uint32_t ahf[4][4], alf[4][4], bhf[2][4], blf[2][4];
#pragma unroll
            for (int mi = 0; mi < 4; mi++) {
                const uint32_t ra = (uint32_t)((arow + mi * 16) * 128);
                LDSM4(ahf[mi], tAh + ra + offA);
                LDSM4(alf[mi], tAl + ra + offA);
            }
#pragma unroll
            for (int j = 0; j < 2; j++) {
                const uint32_t rb = (uint32_t)((brow + j * 16) * 128);
                LDSM4(bhf[j], tWh + rb + offB);
                LDSM4(blf[j], tWl + rb + offB);
            }
#pragma unroll
            for (int mi = 0; mi < 4; mi++) {
#pragma unroll
                for (int ni = 0; ni < 4; ni++) {
                    const uint32_t* bh = &bhf[ni >> 1][(ni & 1) * 2];
                    const uint32_t* bl = &blf[ni >> 1][(ni & 1) * 2];
                    MMA16816(c[mi][ni], ahf[mi], bh[0], bh[1]);
                    MMA16816(c[mi][ni], ahf[mi], bl[0], bl[1]);
                    MMA16816(c[mi][ni], alf[mi], bh[0], bh[1]);
                }
            }
        }
        mbar_arrive(bempty[s]);
    }

    const int g   = lane >> 2;
    const int tig = lane & 3;
    const long m_base = (long)mb * 128 + wm * 64;
    const long n_base = (long)nb * 128 + wn * 32;
#pragma unroll
    for (int ni = 0; ni < 4; ni++) {
        const long col0 = n_base + ni * 8 + tig * 2;
        const float b0 = bias[col0], b1 = bias[col0 + 1];
#pragma unroll
        for (int mi = 0; mi < 4; mi++) {
            const long r0 = m_base + mi * 16 + g;
            float2 o0, o1;
            o0.x = scale * (c[mi][ni][0] + b0);
            o0.y = scale * (c[mi][ni][1] + b1);
            o1.x = scale * (c[mi][ni][2] + b0);
            o1.y = scale * (c[mi][ni][3] + b1);
            *reinterpret_cast<float2*>(C + r0 * D_MODEL + col0)       = o0;
            *reinterpret_cast<float2*>(C + (r0 + 8) * D_MODEL + col0) = o1;
        }
    }
}

// ---------------- attention over L=8 per n; emits split(ao) into blocked A tiles ----------------
// ROWP=1028 (1028 % 32 == 4): conflict-free score phase (8 m-rows hit distinct banks).
#define ROWP 1028
#define ATTN_SMEM ((3 * 8 * ROWP + 1024) * 4)   // 102784 bytes

__global__ void __launch_bounds__(256) attention_kernel(
    const float* __restrict__ q, const float* __restrict__ k,
    const float* __restrict__ v,
    char* __restrict__ aoh, char* __restrict__ aol,
    float* __restrict__ weights_out)
{
    extern __shared__ float sm[];
    float* qs  = sm;
    float* ks  = qs + 8 * ROWP;
    float* vs  = ks + 8 * ROWP;
    float* scr = vs + 8 * ROWP;        // [h][l][m] = 1024

    const int n = blockIdx.x;
    const int tid = threadIdx.x;

    for (int idx = tid; idx < 8 * 1024; idx += 256) {
        int l = idx >> 10, c = idx & 1023;
        size_t g = ((size_t)(l * SEQ + n)) * D_MODEL + c;
        qs[l * ROWP + c] = q[g];
        ks[l * ROWP + c] = k[g];
        vs[l * ROWP + c] = v[g];
    }
    __syncthreads();

    for (int t = tid; t < 1024; t += 256) {
        int h = t >> 6, l = (t >> 3) & 7, m = t & 7;
        const float* qp = qs + l * ROWP + h * HDIM;
        const float* kp = ks + m * ROWP + h * HDIM;
        float s = 0.f;
#pragma unroll
        for (int d = 0; d < HDIM; d++) s += qp[d] * kp[d];
        scr[t] = s;
    }
    __syncthreads();

    if (tid < 128) {
        float* rowp = scr + tid * 8;
        float mx = rowp[0];
#pragma unroll
        for (int m = 1; m < 8; m++) mx = fmaxf(mx, rowp[m]);
        float e[8], ssum = 0.f;
#pragma unroll
        for (int m = 0; m < 8; m++) { e[m] = __expf(rowp[m] - mx); ssum += e[m]; }
        float inv = 1.f / ssum;
#pragma unroll
        for (int m = 0; m < 8; m++) rowp[m] = e[m] * inv;
    }
    __syncthreads();

    if (weights_out != nullptr && tid < 64) {
        float s = 0.f;
#pragma unroll
        for (int h = 0; h < 16; h++) s += scr[h * 64 + tid];
        weights_out[(size_t)n * 64 + tid] = s * (1.f / 16.f);
    }

    // ao[l, c] = sum_m attn[h(c)][l][m] * v[m, c]; write bf16 split into blocked tiles
    const int nrow = n & 127;          // row within 128-row block
    const int nblk = n >> 7;           // which block along S
    for (int t = tid; t < 8 * 512; t += 256) {
        int l  = t >> 9;
        int cp = (t & 511) * 2;
        int h  = cp >> 6;
        const float* a = scr + h * 64 + l * 8;
        float s0 = 0.f, s1 = 0.f;
#pragma unroll
        for (int m = 0; m < 8; m++) {
            float2 vv = *reinterpret_cast<const float2*>(vs + m * ROWP + cp);
            s0 += a[m] * vv.x;
            s1 += a[m] * vv.y;
        }
        float r0, r1;
        uint32_t hp = split_pack_hi(s0, s1, r0, r1);
        uint32_t lp = pack_bf16(r0, r1);

        int mb  = l * 32 + nblk;               // (l*4096+n)>>7
        int kc  = cp >> 6;
        int col = cp & 63;
        uint32_t off = swz128((uint32_t)(nrow * 128 + col * 2));
        size_t tb = ((size_t)mb * 16 + kc) * 16384;
        *reinterpret_cast<uint32_t*>(aoh + tb + off) = hp;
        *reinterpret_cast<uint32_t*>(aol + tb + off) = lp;
    }
}

// ---------------- launch ----------------
extern "C" void kernel_launch(void* const* d_in, const int* in_sizes, int n_in,
                              void* d_out, int out_size)
{
    const float* query = (const float*)d_in[0];
    // d_in[1] = key : unused (reference aliasing bug — both pooled tensors are value)
    const float* value = (const float*)d_in[2];
    const float* in_w  = (const float*)d_in[3];
    const float* in_b  = (const float*)d_in[4];
    const float* out_w = (const float*)d_in[5];
    const float* out_b = (const float*)d_in[6];

    float* out = (float*)d_out;
    float* wts = ((size_t)out_size >= OUT_ELEMS + W_ELEMS) ? out + OUT_ELEMS : nullptr;

    float *q, *k, *v;
    __nv_bfloat16 *Ah, *Al, *Qh, *Ql, *Wh, *Wl;
    cudaGetSymbolAddress((void**)&q,  g_q);
    cudaGetSymbolAddress((void**)&k,  g_k);
    cudaGetSymbolAddress((void**)&v,  g_v);
    cudaGetSymbolAddress((void**)&Ah, g_Ah);
    cudaGetSymbolAddress((void**)&Al, g_Al);
    cudaGetSymbolAddress((void**)&Qh, g_Qh);
    cudaGetSymbolAddress((void**)&Ql, g_Ql);
    cudaGetSymbolAddress((void**)&Wh, g_Wh);
    cudaGetSymbolAddress((void**)&Wl, g_Wl);

    cudaFuncSetAttribute(gemm_mma_kernel,
                         cudaFuncAttributeMaxDynamicSharedMemorySize, GEMM_SMEM);
    cudaFuncSetAttribute(attention_kernel,
                         cudaFuncAttributeMaxDynamicSharedMemorySize, ATTN_SMEM);

    const size_t WS = 1024u * 1024u;   // elems per weight slot

    // --- weight conversion: slots 0,1,2 = Wq,Wk,Wv ; slot 3 = Wo ---
    convert_split_kernel<<<(3072 * 128) / 256, 256>>>(in_w, (char*)Wh, (char*)Wl);
    convert_split_kernel<<<(1024 * 128) / 256, 256>>>(out_w, (char*)(Wh + 3 * WS),
                                                      (char*)(Wl + 3 * WS));

    // --- activations ---
    // kv = window_mean(value), split directly into Ah/Al
    window_mean_split_kernel<<<BATCH * 32, 512>>>(value, (char*)Ah, (char*)Al);
    // query split
    convert_split_kernel<<<(MROWS * 128) / 256, 256>>>(query, (char*)Qh, (char*)Ql);

    dim3 gg(8, 256);
    // q = (query @ Wq^T + bq) / 8
    gemm_mma_kernel<<<gg, 256, GEMM_SMEM>>>(Qh, Ql, Wh, Wl, in_b, q, 0.125f);
    // k = kv @ Wk^T + bk
    gemm_mma_kernel<<<gg, 256, GEMM_SMEM>>>(Ah, Al, Wh + WS, Wl + WS,
                                            in_b + D_MODEL, k, 1.0f);
    // v = kv @ Wv^T + bv
    gemm_mma_kernel<<<gg, 256, GEMM_SMEM>>>(Ah, Al, Wh + 2 * WS, Wl + 2 * WS,
                                            in_b + 2 * D_MODEL, v, 1.0f);

    // attention: ao = attn @ v, emitted as bf16 split into Qh/Ql (reused), + weights
    attention_kernel<<<SEQ, 256, ATTN_SMEM>>>(q, k, v, (char*)Qh, (char*)Ql, wts);

    // out = ao @ Wo^T + bo -> d_out
    gemm_mma_kernel<<<gg, 256, GEMM_SMEM>>>(Qh, Ql, Wh + 3 * WS, Wl + 3 * WS,
                                            out_b, out, 1.0f);
}

// round 7
// speedup vs baseline: 3.2466x; 1.0161x over previous
#include <cuda_runtime.h>
#include <cuda_bf16.h>
#include <cstdint>

// ---------------- problem constants ----------------
#define D_MODEL 1024
#define SEQ     4096
#define BATCH   8
#define HDIM    64
#define WIN     128
#define MROWS   (BATCH * SEQ)                          // 32768
#define OUT_ELEMS ((size_t)MROWS * D_MODEL)            // 33554432
#define W_ELEMS   ((size_t)SEQ * 64)                   // 262144

// ---------------- scratch (static device globals) ----------------
__device__ float g_q [OUT_ELEMS];
__device__ float g_k [OUT_ELEMS];
__device__ float g_v [OUT_ELEMS];
__device__ __nv_bfloat16 g_Ah[OUT_ELEMS];   // kv split
__device__ __nv_bfloat16 g_Al[OUT_ELEMS];
__device__ __nv_bfloat16 g_Qh[OUT_ELEMS];   // query split, then ao split
__device__ __nv_bfloat16 g_Ql[OUT_ELEMS];
__device__ __nv_bfloat16 g_Wh[4u * 1024u * 1024u];   // slots: 0=Wq 1=Wk 2=Wv 3=Wo
__device__ __nv_bfloat16 g_Wl[4u * 1024u * 1024u];

// ---------------- PTX helpers (sm_90 baseline features only) ----------------
__device__ __forceinline__ uint32_t smem_u32(const void* p) {
    uint32_t a;
    asm("{ .reg .u64 t; cvta.to.shared.u64 t, %1; cvt.u32.u64 %0, t; }" : "=r"(a) : "l"(p));
    return a;
}
__device__ __forceinline__ void mbar_init(uint32_t m, uint32_t cnt) {
    asm volatile("mbarrier.init.shared.b64 [%0], %1;" :: "r"(m), "r"(cnt) : "memory");
}
__device__ __forceinline__ void mbar_expect_tx(uint32_t m, uint32_t bytes) {
    asm volatile("mbarrier.arrive.expect_tx.shared.b64 _, [%0], %1;" :: "r"(m), "r"(bytes) : "memory");
}
__device__ __forceinline__ void mbar_arrive(uint32_t m) {
    asm volatile("mbarrier.arrive.shared.b64 _, [%0];" :: "r"(m) : "memory");
}
__device__ __forceinline__ void mbar_wait(uint32_t m, uint32_t parity) {
    asm volatile(
        "{\n\t.reg .pred P;\n\t"
        "WL_%=:\n\t"
        "mbarrier.try_wait.parity.acquire.cta.shared::cta.b64 P, [%0], %1, 0x989680;\n\t"
        "@P bra.uni WD_%=;\n\t"
        "bra.uni WL_%=;\n\t"
        "WD_%=:\n\t}"
        :: "r"(m), "r"(parity) : "memory");
}
__device__ __forceinline__ void bulk_g2s(uint32_t dst, const void* src, uint32_t bytes, uint32_t mbar) {
    asm volatile(
        "cp.async.bulk.shared::cluster.global.mbarrier::complete_tx::bytes [%0], [%1], %2, [%3];"
        :: "r"(dst), "l"(src), "r"(bytes), "r"(mbar) : "memory");
}

#define LDSM4(r, a) \
    asm volatile("ldmatrix.sync.aligned.m8n8.x4.shared.b16 {%0,%1,%2,%3}, [%4];" \
        : "=r"((r)[0]), "=r"((r)[1]), "=r"((r)[2]), "=r"((r)[3]) : "r"(a))

#define MMA16816(c, a, b0, b1) \
    asm volatile("mma.sync.aligned.m16n8k16.row.col.f32.bf16.bf16.f32 " \
        "{%0,%1,%2,%3}, {%4,%5,%6,%7}, {%8,%9}, {%0,%1,%2,%3};" \
        : "+f"((c)[0]), "+f"((c)[1]), "+f"((c)[2]), "+f"((c)[3]) \
        : "r"((a)[0]), "r"((a)[1]), "r"((a)[2]), "r"((a)[3]), "r"(b0), "r"(b1))

__host__ __device__ __forceinline__ uint32_t swz128(uint32_t o) { return o ^ ((o >> 3) & 0x70); }

__device__ __forceinline__ uint32_t split_pack_hi(float f0, float f1,
                                                  float& r0, float& r1) {
    __nv_bfloat16 h0 = __float2bfloat16_rn(f0);
    __nv_bfloat16 h1 = __float2bfloat16_rn(f1);
    r0 = f0 - __bfloat162float(h0);
    r1 = f1 - __bfloat162float(h1);
    unsigned short u0 = *reinterpret_cast<unsigned short*>(&h0);
    unsigned short u1 = *reinterpret_cast<unsigned short*>(&h1);
    return (uint32_t)u0 | ((uint32_t)u1 << 16);
}
__device__ __forceinline__ uint32_t pack_bf16(float f0, float f1) {
    __nv_bfloat16 h0 = __float2bfloat16_rn(f0);
    __nv_bfloat16 h1 = __float2bfloat16_rn(f1);
    unsigned short u0 = *reinterpret_cast<unsigned short*>(&h0);
    unsigned short u1 = *reinterpret_cast<unsigned short*>(&h1);
    return (uint32_t)u0 | ((uint32_t)u1 << 16);
}

// ---------------- window mean fused with bf16 split ----------------
__global__ void __launch_bounds__(512) window_mean_split_kernel(
    const float* __restrict__ val, char* __restrict__ hi, char* __restrict__ lo)
{
    int blk   = blockIdx.x;
    int chunk = blk & 31;
    int b     = blk >> 5;
    int d     = threadIdx.x * 2;

    const float2* base = reinterpret_cast<const float2*>(
        val + ((size_t)b * SEQ) * D_MODEL + d);

    int s0 = chunk * 128;
    int l  = max(s0 - WIN, 0);
    int r  = min(s0 + WIN + 1, SEQ);

    float sx = 0.f, sy = 0.f;
    for (int j = l; j < r; j++) {
        float2 t = base[(size_t)j * (D_MODEL / 2)];
        sx += t.x; sy += t.y;
    }

    const int kc  = d >> 6;
    const int col = d & 63;
    for (int s = s0; s < s0 + 128; s++) {
        if (s > s0) {
            int rn = s + WIN + 1;
            if (rn <= SEQ) {
                float2 t = base[(size_t)(rn - 1) * (D_MODEL / 2)];
                sx += t.x; sy += t.y; r = rn;
            }
            int ln = s - WIN;
            if (ln > 0) {
                float2 t = base[(size_t)(ln - 1) * (D_MODEL / 2)];
                sx -= t.x; sy -= t.y; l = ln;
            }
        }
        float inv = 1.f / (float)(r - l);
        float m0 = sx * inv, m1 = sy * inv;
        float r0, r1;
        uint32_t hp = split_pack_hi(m0, m1, r0, r1);
        uint32_t lp = pack_bf16(r0, r1);

        int m   = b * SEQ + s;
        int mb  = m >> 7, row = m & 127;
        uint32_t off = swz128((uint32_t)(row * 128 + col * 2));
        size_t tb = ((size_t)mb * 16 + kc) * 16384;
        *reinterpret_cast<uint32_t*>(hi + tb + off) = hp;
        *reinterpret_cast<uint32_t*>(lo + tb + off) = lp;
    }
}

// ---------------- fp32 -> (bf16 hi, bf16 lo), 128-row tiles, pre-SW128-swizzled ----------------
__global__ void __launch_bounds__(256) convert_split_kernel(
    const float* __restrict__ x, char* __restrict__ hi, char* __restrict__ lo)
{
    size_t idx = (size_t)blockIdx.x * 256 + threadIdx.x;   // one per 8 elements
    int m = (int)(idx >> 7);
    int k = (int)(idx & 127) << 3;

    const float4* p = reinterpret_cast<const float4*>(x + (size_t)m * 1024 + k);
    float4 f0 = p[0], f1 = p[1];
    float f[8] = {f0.x, f0.y, f0.z, f0.w, f1.x, f1.y, f1.z, f1.w};

    uint32_t hp[4], lp[4];
#pragma unroll
    for (int i = 0; i < 4; i++) {
        float r0, r1;
        hp[i] = split_pack_hi(f[2*i], f[2*i+1], r0, r1);
        lp[i] = pack_bf16(r0, r1);
    }

    int mb  = m >> 7;
    int row = m & 127;
    int kc  = k >> 6;
    int col = k & 63;
    uint32_t off = swz128((uint32_t)(row * 128 + col * 2));
    size_t tb = ((size_t)mb * 16 + kc) * 16384;

    *reinterpret_cast<uint4*>(hi + tb + off) = make_uint4(hp[0], hp[1], hp[2], hp[3]);
    *reinterpret_cast<uint4*>(lo + tb + off) = make_uint4(lp[0], lp[1], lp[2], lp[3]);
}

// ---------------- mma.sync GEMM: C[m,n] = scale*(sum_k A[m,k]*W[n,k] + bias[n]) ----------------
#define STAGE_BYTES 65536
#define NSTAGE 3
#define GEMM_SMEM (NSTAGE * STAGE_BYTES + 1024)

__global__ void __launch_bounds__(256, 1) gemm_mma_kernel(
    const __nv_bfloat16* __restrict__ Ah, const __nv_bfloat16* __restrict__ Al,
    const __nv_bfloat16* __restrict__ Wh, const __nv_bfloat16* __restrict__ Wl,
    const float* __restrict__ bias, float* __restrict__ C, float scale)
{
    extern __shared__ char dsm[];
    __shared__ __align__(8) uint64_t bars[2 * NSTAGE];

    const int tid  = threadIdx.x;
    const int lane = tid & 31;
    const int w    = tid >> 5;
    const int wm   = w & 1;
    const int wn   = w >> 1;

    const uint32_t smraw = smem_u32(dsm);
    const uint32_t base  = (smraw + 1023u) & ~1023u;

    if (tid == 0) {
        for (int i = 0; i < NSTAGE; i++) {
            mbar_init(smem_u32(&bars[i]), 1);
            mbar_init(smem_u32(&bars[NSTAGE + i]), 256);
        }
        asm volatile("fence.proxy.async.shared::cta;" ::: "memory");
    }
    __syncthreads();

    uint32_t bfull[NSTAGE], bempty[NSTAGE];
#pragma unroll
    for (int i = 0; i < NSTAGE; i++) {
        bfull[i]  = smem_u32(&bars[i]);
        bempty[i] = smem_u32(&bars[NSTAGE + i]);
    }

    const int nb = blockIdx.x;
    const int mb = blockIdx.y;
    const char* ah = (const char*)Ah + (size_t)mb * 16 * 16384;
    const char* al = (const char*)Al + (size_t)mb * 16 * 16384;
    const char* wh = (const char*)Wh + (size_t)nb * 16 * 16384;
    const char* wl = (const char*)Wl + (size_t)nb * 16 * 16384;

    if (tid == 0) {
#pragma unroll
        for (int p = 0; p < 2; p++) {
            const uint32_t st = base + p * STAGE_BYTES;
            mbar_expect_tx(bfull[p], STAGE_BYTES);
            bulk_g2s(st,         ah + (size_t)p * 16384, 16384, bfull[p]);
            bulk_g2s(st + 16384, al + (size_t)p * 16384, 16384, bfull[p]);
            bulk_g2s(st + 32768, wh + (size_t)p * 16384, 16384, bfull[p]);
            bulk_g2s(st + 49152, wl + (size_t)p * 16384, 16384, bfull[p]);
        }
    }

    const int r3 = lane & 7;
    const uint32_t xr = (uint32_t)(r3 << 4);
    const int arow = wm * 64 + r3 + ((lane >> 3) & 1) * 8;
    const uint32_t akh = (uint32_t)((lane >> 4) << 4);
    const int brow = wn * 32 + (lane >> 4) * 8 + r3;
    const uint32_t bkh = (uint32_t)(((lane >> 3) & 1) << 4);

    float c[4][4][4];
#pragma unroll
    for (int mi = 0; mi < 4; mi++)
#pragma unroll
        for (int ni = 0; ni < 4; ni++)
#pragma unroll
            for (int j = 0; j < 4; j++) c[mi][ni][j] = 0.f;

    for (int t = 0; t < 16; t++) {
        const int s = t % 3;
        if (tid == 0 && t + 2 < 16) {
            const int s2 = (t + 2) % 3;
            mbar_wait(bempty[s2], (uint32_t)((((t + 2) / 3) & 1) ^ 1));
            mbar_expect_tx(bfull[s2], STAGE_BYTES);
            const uint32_t st = base + s2 * STAGE_BYTES;
            bulk_g2s(st,         ah + (size_t)(t + 2) * 16384, 16384, bfull[s2]);
            bulk_g2s(st + 16384, al + (size_t)(t + 2) * 16384, 16384, bfull[s2]);
            bulk_g2s(st + 32768, wh + (size_t)(t + 2) * 16384, 16384, bfull[s2]);
            bulk_g2s(st + 49152, wl + (size_t)(t + 2) * 16384, 16384, bfull[s2]);
        }
        mbar_wait(bfull[s], (uint32_t)((t / 3) & 1));

        const uint32_t st  = base + s * STAGE_BYTES;
        const uint32_t tAh = st, tAl = st + 16384, tWh = st + 32768, tWl = st + 49152;

#pragma unroll
        for (int ks = 0; ks < 4; ks++) {
            const uint32_t offA = ((uint32_t)(ks * 32) + akh) ^ xr;
            const uint32_t offB = ((uint32_t)(ks * 32) + bkh) ^ xr;

            uint32_t ahf[4][4], alf[4][4], bhf[2][4], blf[2][4];
#pragma unroll
            for (int mi = 0; mi < 4; mi++) {
                const uint32_t ra = (uint32_t)((arow + mi * 16) * 128);
                LDSM4(ahf[mi], tAh + ra + offA);
                LDSM4(alf[mi], tAl + ra + offA);
            }
#pragma unroll
            for (int j = 0; j < 2; j++) {
                const uint32_t rb = (uint32_t)((brow + j * 16) * 128);
                LDSM4(bhf[j], tWh + rb + offB);
                LDSM4(blf[j], tWl + rb + offB);
            }
            // term-major issue order: 16 independent accumulators between any
            // two MMAs that hit the same c[mi][ni] -> no RAW stalls.
#pragma unroll
            for (int mi = 0; mi < 4; mi++) {
#pragma unroll
                for (int ni = 0; ni < 4; ni++) {
                    const uint32_t* bh = &bhf[ni >> 1][(ni & 1) * 2];
                    MMA16816(c[mi][ni], ahf[mi], bh[0], bh[1]);
                }
            }
#pragma unroll
            for (int mi = 0; mi < 4; mi++) {
#pragma unroll
                for (int ni = 0; ni < 4; ni++) {
                    const uint32_t* bl = &blf[ni >> 1][(ni & 1) * 2];
                    MMA16816(c[mi][ni], ahf[mi], bl[0], bl[1]);
                }
            }
#pragma unroll
            for (int mi = 0; mi < 4; mi++) {
#pragma unroll
                for (int ni = 0; ni < 4; ni++) {
                    const uint32_t* bh = &bhf[ni >> 1][(ni & 1) * 2];
                    MMA16816(c[mi][ni], alf[mi], bh[0], bh[1]);
                }
            }
        }
        mbar_arrive(bempty[s]);
    }

    const int g   = lane >> 2;
    const int tig = lane & 3;
    const long m_base = (long)mb * 128 + wm * 64;
    const long n_base = (long)nb * 128 + wn * 32;
#pragma unroll
    for (int ni = 0; ni < 4; ni++) {
        const long col0 = n_base + ni * 8 + tig * 2;
        const float b0 = bias[col0], b1 = bias[col0 + 1];
#pragma unroll
        for (int mi = 0; mi < 4; mi++) {
            const long r0 = m_base + mi * 16 + g;
            float2 o0, o1;
            o0.x = scale * (c[mi][ni][0] + b0);
            o0.y = scale * (c[mi][ni][1] + b1);
            o1.x = scale * (c[mi][ni][2] + b0);
            o1.y = scale * (c[mi][ni][3] + b1);
            *reinterpret_cast<float2*>(C + r0 * D_MODEL + col0)       = o0;
            *reinterpret_cast<float2*>(C + (r0 + 8) * D_MODEL + col0) = o1;
        }
    }
}

// ---------------- attention over L=8 per n; emits split(ao) into blocked A tiles ----------------
// ROWP=1028 (1028 % 32 == 4): conflict-free score phase (8 m-rows hit distinct banks).
#define ROWP 1028
#define ATTN_SMEM ((3 * 8 * ROWP + 1024) * 4)   // 102784 bytes

__global__ void __launch_bounds__(256) attention_kernel(
    const float* __restrict__ q, const float* __restrict__ k,
    const float* __restrict__ v,
    char* __restrict__ aoh, char* __restrict__ aol,
    float* __restrict__ weights_out)
{
    extern __shared__ float sm[];
    float* qs  = sm;
    float* ks  = qs + 8 * ROWP;
    float* vs  = ks + 8 * ROWP;
    float* scr = vs + 8 * ROWP;        // [h][l][m] = 1024

    const int n = blockIdx.x;
    const int tid = threadIdx.x;

    for (int idx = tid; idx < 8 * 1024; idx += 256) {
        int l = idx >> 10, c = idx & 1023;
        size_t g = ((size_t)(l * SEQ + n)) * D_MODEL + c;
        qs[l * ROWP + c] = q[g];
        ks[l * ROWP + c] = k[g];
        vs[l * ROWP + c] = v[g];
    }
    __syncthreads();

    for (int t = tid; t < 1024; t += 256) {
        int h = t >> 6, l = (t >> 3) & 7, m = t & 7;
        const float* qp = qs + l * ROWP + h * HDIM;
        const float* kp = ks + m * ROWP + h * HDIM;
        float s = 0.f;
#pragma unroll
        for (int d = 0; d < HDIM; d++) s += qp[d] * kp[d];
        scr[t] = s;
    }
    __syncthreads();

    if (tid < 128) {
        float* rowp = scr + tid * 8;
        float mx = rowp[0];
#pragma unroll
        for (int m = 1; m < 8; m++) mx = fmaxf(mx, rowp[m]);
        float e[8], ssum = 0.f;
#pragma unroll
        for (int m = 0; m < 8; m++) { e[m] = __expf(rowp[m] - mx); ssum += e[m]; }
        float inv = 1.f / ssum;
#pragma unroll
        for (int m = 0; m < 8; m++) rowp[m] = e[m] * inv;
    }
    __syncthreads();

    if (weights_out != nullptr && tid < 64) {
        float s = 0.f;
#pragma unroll
        for (int h = 0; h < 16; h++) s += scr[h * 64 + tid];
        weights_out[(size_t)n * 64 + tid] = s * (1.f / 16.f);
    }

    // ao[l, c] = sum_m attn[h(c)][l][m] * v[m, c]; write bf16 split into blocked tiles
    const int nrow = n & 127;
    const int nblk = n >> 7;
    for (int t = tid; t < 8 * 512; t += 256) {
        int l  = t >> 9;
        int cp = (t & 511) * 2;
        int h  = cp >> 6;
        const float* a = scr + h * 64 + l * 8;
        float s0 = 0.f, s1 = 0.f;
#pragma unroll
        for (int m = 0; m < 8; m++) {
            float2 vv = *reinterpret_cast<const float2*>(vs + m * ROWP + cp);
            s0 += a[m] * vv.x;
            s1 += a[m] * vv.y;
        }
        float r0, r1;
        uint32_t hp = split_pack_hi(s0, s1, r0, r1);
        uint32_t lp = pack_bf16(r0, r1);

        int mb  = l * 32 + nblk;
        int kc  = cp >> 6;
        int col = cp & 63;
        uint32_t off = swz128((uint32_t)(nrow * 128 + col * 2));
        size_t tb = ((size_t)mb * 16 + kc) * 16384;
        *reinterpret_cast<uint32_t*>(aoh + tb + off) = hp;
        *reinterpret_cast<uint32_t*>(aol + tb + off) = lp;
    }
}

// ---------------- launch ----------------
extern "C" void kernel_launch(void* const* d_in, const int* in_sizes, int n_in,
                              void* d_out, int out_size)
{
    const float* query = (const float*)d_in[0];
    // d_in[1] = key : unused (reference aliasing bug — both pooled tensors are value)
    const float* value = (const float*)d_in[2];
    const float* in_w  = (const float*)d_in[3];
    const float* in_b  = (const float*)d_in[4];
    const float* out_w = (const float*)d_in[5];
    const float* out_b = (const float*)d_in[6];

    float* out = (float*)d_out;
    float* wts = ((size_t)out_size >= OUT_ELEMS + W_ELEMS) ? out + OUT_ELEMS : nullptr;

    float *q, *k, *v;
    __nv_bfloat16 *Ah, *Al, *Qh, *Ql, *Wh, *Wl;
    cudaGetSymbolAddress((void**)&q,  g_q);
    cudaGetSymbolAddress((void**)&k,  g_k);
    cudaGetSymbolAddress((void**)&v,  g_v);
    cudaGetSymbolAddress((void**)&Ah, g_Ah);
    cudaGetSymbolAddress((void**)&Al, g_Al);
    cudaGetSymbolAddress((void**)&Qh, g_Qh);
    cudaGetSymbolAddress((void**)&Ql, g_Ql);
    cudaGetSymbolAddress((void**)&Wh, g_Wh);
    cudaGetSymbolAddress((void**)&Wl, g_Wl);

    cudaFuncSetAttribute(gemm_mma_kernel,
                         cudaFuncAttributeMaxDynamicSharedMemorySize, GEMM_SMEM);
    cudaFuncSetAttribute(attention_kernel,
                         cudaFuncAttributeMaxDynamicSharedMemorySize, ATTN_SMEM);

    const size_t WS = 1024u * 1024u;   // elems per weight slot

    // --- weight conversion: slots 0,1,2 = Wq,Wk,Wv ; slot 3 = Wo ---
    convert_split_kernel<<<(3072 * 128) / 256, 256>>>(in_w, (char*)Wh, (char*)Wl);
    convert_split_kernel<<<(1024 * 128) / 256, 256>>>(out_w, (char*)(Wh + 3 * WS),
                                                      (char*)(Wl + 3 * WS));

    // --- activations ---
    window_mean_split_kernel<<<BATCH * 32, 512>>>(value, (char*)Ah, (char*)Al);
    convert_split_kernel<<<(MROWS * 128) / 256, 256>>>(query, (char*)Qh, (char*)Ql);

    dim3 gg(8, 256);
    // q = (query @ Wq^T + bq) / 8
    gemm_mma_kernel<<<gg, 256, GEMM_SMEM>>>(Qh, Ql, Wh, Wl, in_b, q, 0.125f);
    // k = kv @ Wk^T + bk
    gemm_mma_kernel<<<gg, 256, GEMM_SMEM>>>(Ah, Al, Wh + WS, Wl + WS,
                                            in_b + D_MODEL, k, 1.0f);
    // v = kv @ Wv^T + bv
    gemm_mma_kernel<<<gg, 256, GEMM_SMEM>>>(Ah, Al, Wh + 2 * WS, Wl + 2 * WS,
                                            in_b + 2 * D_MODEL, v, 1.0f);

    // attention: ao = attn @ v, emitted as bf16 split into Qh/Ql (reused), + weights
    attention_kernel<<<SEQ, 256, ATTN_SMEM>>>(q, k, v, (char*)Qh, (char*)Ql, wts);

    // out = ao @ Wo^T + bo -> d_out
    gemm_mma_kernel<<<gg, 256, GEMM_SMEM>>>(Qh, Ql, Wh + 3 * WS, Wl + 3 * WS,
                                            out_b, out, 1.0f);
}

// round 8
// speedup vs baseline: 4.3099x; 1.3275x over previous
#include <cuda_runtime.h>
#include <cuda_fp16.h>
#include <cstdint>

// ---------------- problem constants ----------------
#define D_MODEL 1024
#define SEQ     4096
#define BATCH   8
#define HDIM    64
#define WIN     128
#define MROWS   (BATCH * SEQ)                          // 32768
#define OUT_ELEMS ((size_t)MROWS * D_MODEL)            // 33554432
#define W_ELEMS   ((size_t)SEQ * 64)                   // 262144

// ---------------- scratch (static device globals) ----------------
__device__ float g_q [OUT_ELEMS];
__device__ float g_k [OUT_ELEMS];
__device__ float g_v [OUT_ELEMS];
__device__ __half g_A [OUT_ELEMS];   // kv fp16, blocked
__device__ __half g_Q [OUT_ELEMS];   // query fp16, then ao fp16, blocked
__device__ __half g_Wh[4u * 1024u * 1024u];   // weight hi slots: 0=Wq 1=Wk 2=Wv 3=Wo
__device__ __half g_Wl[4u * 1024u * 1024u];   // weight lo

// ---------------- PTX helpers ----------------
__device__ __forceinline__ uint32_t smem_u32(const void* p) {
    uint32_t a;
    asm("{ .reg .u64 t; cvta.to.shared.u64 t, %1; cvt.u32.u64 %0, t; }" : "=r"(a) : "l"(p));
    return a;
}
__device__ __forceinline__ void mbar_init(uint32_t m, uint32_t cnt) {
    asm volatile("mbarrier.init.shared.b64 [%0], %1;" :: "r"(m), "r"(cnt) : "memory");
}
__device__ __forceinline__ void mbar_expect_tx(uint32_t m, uint32_t bytes) {
    asm volatile("mbarrier.arrive.expect_tx.shared.b64 _, [%0], %1;" :: "r"(m), "r"(bytes) : "memory");
}
__device__ __forceinline__ void mbar_arrive(uint32_t m) {
    asm volatile("mbarrier.arrive.shared.b64 _, [%0];" :: "r"(m) : "memory");
}
__device__ __forceinline__ void mbar_wait(uint32_t m, uint32_t parity) {
    asm volatile(
        "{\n\t.reg .pred P;\n\t"
        "WL_%=:\n\t"
        "mbarrier.try_wait.parity.acquire.cta.shared::cta.b64 P, [%0], %1, 0x989680;\n\t"
        "@P bra.uni WD_%=;\n\t"
        "bra.uni WL_%=;\n\t"
        "WD_%=:\n\t}"
        :: "r"(m), "r"(parity) : "memory");
}
__device__ __forceinline__ void bulk_g2s(uint32_t dst, const void* src, uint32_t bytes, uint32_t mbar) {
    asm volatile(
        "cp.async.bulk.shared::cluster.global.mbarrier::complete_tx::bytes [%0], [%1], %2, [%3];"
        :: "r"(dst), "l"(src), "r"(bytes), "r"(mbar) : "memory");
}

#define LDSM4(r, a) \
    asm volatile("ldmatrix.sync.aligned.m8n8.x4.shared.b16 {%0,%1,%2,%3}, [%4];" \
        : "=r"((r)[0]), "=r"((r)[1]), "=r"((r)[2]), "=r"((r)[3]) : "r"(a))

#define MMA16816(c, a, b0, b1) \
    asm volatile("mma.sync.aligned.m16n8k16.row.col.f32.f16.f16.f32 " \
        "{%0,%1,%2,%3}, {%4,%5,%6,%7}, {%8,%9}, {%0,%1,%2,%3};" \
        : "+f"((c)[0]), "+f"((c)[1]), "+f"((c)[2]), "+f"((c)[3]) \
        : "r"((a)[0]), "r"((a)[1]), "r"((a)[2]), "r"((a)[3]), "r"(b0), "r"(b1))

__host__ __device__ __forceinline__ uint32_t swz128(uint32_t o) { return o ^ ((o >> 3) & 0x70); }

__device__ __forceinline__ uint32_t pack_h2(float f0, float f1) {
    __half2 h = __floats2half2_rn(f0, f1);
    return *reinterpret_cast<uint32_t*>(&h);
}

// ---------------- window mean fused with fp16 convert ----------------
// Writes fp16(kv) directly into blocked/pre-swizzled A tiles.
__global__ void __launch_bounds__(512) window_mean_h_kernel(
    const float* __restrict__ val, char* __restrict__ dst)
{
    int blk   = blockIdx.x;
    int chunk = blk & 31;
    int b     = blk >> 5;
    int d     = threadIdx.x * 2;

    const float2* base = reinterpret_cast<const float2*>(
        val + ((size_t)b * SEQ) * D_MODEL + d);

    int s0 = chunk * 128;
    int l  = max(s0 - WIN, 0);
    int r  = min(s0 + WIN + 1, SEQ);

    float sx = 0.f, sy = 0.f;
    for (int j = l; j < r; j++) {
        float2 t = base[(size_t)j * (D_MODEL / 2)];
        sx += t.x; sy += t.y;
    }

    const int kc  = d >> 6;
    const int col = d & 63;
    for (int s = s0; s < s0 + 128; s++) {
        if (s > s0) {
            int rn = s + WIN + 1;
            if (rn <= SEQ) {
                float2 t = base[(size_t)(rn - 1) * (D_MODEL / 2)];
                sx += t.x; sy += t.y; r = rn;
            }
            int ln = s - WIN;
            if (ln > 0) {
                float2 t = base[(size_t)(ln - 1) * (D_MODEL / 2)];
                sx -= t.x; sy -= t.y; l = ln;
            }
        }
        float inv = 1.f / (float)(r - l);

        int m   = b * SEQ + s;
        int mb  = m >> 7, row = m & 127;
        uint32_t off = swz128((uint32_t)(row * 128 + col * 2));
        size_t tb = ((size_t)mb * 16 + kc) * 16384;
        *reinterpret_cast<uint32_t*>(dst + tb + off) = pack_h2(sx * inv, sy * inv);
    }
}

// ---------------- fp32 -> fp16, 128-row tiles, pre-SW128-swizzled ----------------
__global__ void __launch_bounds__(256) convert_h_kernel(
    const float* __restrict__ x, char* __restrict__ dst)
{
    size_t idx = (size_t)blockIdx.x * 256 + threadIdx.x;   // one per 8 elements
    int m = (int)(idx >> 7);
    int k = (int)(idx & 127) << 3;

    const float4* p = reinterpret_cast<const float4*>(x + (size_t)m * 1024 + k);
    float4 f0 = p[0], f1 = p[1];

    uint4 o;
    o.x = pack_h2(f0.x, f0.y);
    o.y = pack_h2(f0.z, f0.w);
    o.z = pack_h2(f1.x, f1.y);
    o.w = pack_h2(f1.z, f1.w);

    int mb  = m >> 7;
    int row = m & 127;
    int kc  = k >> 6;
    int col = k & 63;
    uint32_t off = swz128((uint32_t)(row * 128 + col * 2));
    size_t tb = ((size_t)mb * 16 + kc) * 16384;
    *reinterpret_cast<uint4*>(dst + tb + off) = o;
}

// ---------------- weight fp32 -> (fp16 hi, fp16 lo) split, blocked ----------------
__global__ void __launch_bounds__(256) convert_wsplit_kernel(
    const float* __restrict__ x, char* __restrict__ hi, char* __restrict__ lo)
{
    size_t idx = (size_t)blockIdx.x * 256 + threadIdx.x;
    int m = (int)(idx >> 7);
    int k = (int)(idx & 127) << 3;

    const float4* p = reinterpret_cast<const float4*>(x + (size_t)m * 1024 + k);
    float4 f0 = p[0], f1 = p[1];
    float f[8] = {f0.x, f0.y, f0.z, f0.w, f1.x, f1.y, f1.z, f1.w};

    uint32_t hp[4], lp[4];
#pragma unroll
    for (int i = 0; i < 4; i++) {
        __half h0 = __float2half_rn(f[2*i]);
        __half h1 = __float2half_rn(f[2*i+1]);
        float r0 = f[2*i]   - __half2float(h0);
        float r1 = f[2*i+1] - __half2float(h1);
        __half2 hh = __halves2half2(h0, h1);
        hp[i] = *reinterpret_cast<uint32_t*>(&hh);
        lp[i] = pack_h2(r0, r1);
    }

    int mb  = m >> 7;
    int row = m & 127;
    int kc  = k >> 6;
    int col = k & 63;
    uint32_t off = swz128((uint32_t)(row * 128 + col * 2));
    size_t tb = ((size_t)mb * 16 + kc) * 16384;

    *reinterpret_cast<uint4*>(hi + tb + off) = make_uint4(hp[0], hp[1], hp[2], hp[3]);
    *reinterpret_cast<uint4*>(lo + tb + off) = make_uint4(lp[0], lp[1], lp[2], lp[3]);
}

// ---------------- mma.sync GEMM: C[m,n] = scale*(sum_k A[m,k]*W[n,k] + bias[n]) ----------------
// A fp16 blocked; W split (Wh,Wl) fp16 blocked. 2-term: A*Wh + A*Wl.
#define STAGE_BYTES 49152
#define NSTAGE 3
#define GEMM_SMEM (NSTAGE * STAGE_BYTES + 1024)

__global__ void __launch_bounds__(256, 1) gemm_mma_kernel(
    const __half* __restrict__ A,
    const __half* __restrict__ Wh, const __half* __restrict__ Wl,
    const float* __restrict__ bias, float* __restrict__ C, float scale)
{
    extern __shared__ char dsm[];
    __shared__ __align__(8) uint64_t bars[2 * NSTAGE];

    const int tid  = threadIdx.x;
    const int lane = tid & 31;
    const int w    = tid >> 5;
    const int wm   = w & 1;
    const int wn   = w >> 1;

    const uint32_t smraw = smem_u32(dsm);
    const uint32_t base  = (smraw + 1023u) & ~1023u;

    if (tid == 0) {
        for (int i = 0; i < NSTAGE; i++) {
            mbar_init(smem_u32(&bars[i]), 1);
            mbar_init(smem_u32(&bars[NSTAGE + i]), 256);
        }
        asm volatile("fence.proxy.async.shared::cta;" ::: "memory");
    }
    __syncthreads();

    uint32_t bfull[NSTAGE], bempty[NSTAGE];
#pragma unroll
    for (int i = 0; i < NSTAGE; i++) {
        bfull[i]  = smem_u32(&bars[i]);
        bempty[i] = smem_u32(&bars[NSTAGE + i]);
    }

    const int nb = blockIdx.x;
    const int mb = blockIdx.y;
    const char* ap = (const char*)A  + (size_t)mb * 16 * 16384;
    const char* wh = (const char*)Wh + (size_t)nb * 16 * 16384;
    const char* wl = (const char*)Wl + (size_t)nb * 16 * 16384;

    if (tid == 0) {
#pragma unroll
        for (int p = 0; p < 2; p++) {
            const uint32_t st = base + p * STAGE_BYTES;
            mbar_expect_tx(bfull[p], STAGE_BYTES);
            bulk_g2s(st,         ap + (size_t)p * 16384, 16384, bfull[p]);
            bulk_g2s(st + 16384, wh + (size_t)p * 16384, 16384, bfull[p]);
            bulk_g2s(st + 32768, wl + (size_t)p * 16384, 16384, bfull[p]);
        }
    }

    const int r3 = lane & 7;
    const uint32_t xr = (uint32_t)(r3 << 4);
    const int arow = wm * 64 + r3 + ((lane >> 3) & 1) * 8;
    const uint32_t akh = (uint32_t)((lane >> 4) << 4);
    const int brow = wn * 32 + (lane >> 4) * 8 + r3;
    const uint32_t bkh = (uint32_t)(((lane >> 3) & 1) << 4);

    float c[4][4][4];
#pragma unroll
    for (int mi = 0; mi < 4; mi++)
#pragma unroll
        for (int ni = 0; ni < 4; ni++)
#pragma unroll
            for (int j = 0; j < 4; j++) c[mi][ni][j] = 0.f;

    for (int t = 0; t < 16; t++) {
        const int s = t % 3;
        if (tid == 0 && t + 2 < 16) {
            const int s2 = (t + 2) % 3;
            mbar_wait(bempty[s2], (uint32_t)((((t + 2) / 3) & 1) ^ 1));
            mbar_expect_tx(bfull[s2], STAGE_BYTES);
            const uint32_t st = base + s2 * STAGE_BYTES;
            bulk_g2s(st,         ap + (size_t)(t + 2) * 16384, 16384, bfull[s2]);
            bulk_g2s(st + 16384, wh + (size_t)(t + 2) * 16384, 16384, bfull[s2]);
            bulk_g2s(st + 32768, wl + (size_t)(t + 2) * 16384, 16384, bfull[s2]);
        }
        mbar_wait(bfull[s], (uint32_t)((t / 3) & 1));

        const uint32_t st  = base + s * STAGE_BYTES;
        const uint32_t tA = st, tWh = st + 16384, tWl = st + 32768;

#pragma unroll
        for (int ks = 0; ks < 4; ks++) {
            const uint32_t offA = ((uint32_t)(ks * 32) + akh) ^ xr;
            const uint32_t offB = ((uint32_t)(ks * 32) + bkh) ^ xr;

            uint32_t af[4][4], bhf[2][4], blf[2][4];
#pragma unroll
            for (int mi = 0; mi < 4; mi++) {
                const uint32_t ra = (uint32_t)((arow + mi * 16) * 128);
                LDSM4(af[mi], tA + ra + offA);
            }
#pragma unroll
            for (int j = 0; j < 2; j++) {
                const uint32_t rb = (uint32_t)((brow + j * 16) * 128);
                LDSM4(bhf[j], tWh + rb + offB);
                LDSM4(blf[j], tWl + rb + offB);
            }
            // term-major: 16 independent accumulators between revisits
#pragma unroll
            for (int mi = 0; mi < 4; mi++) {
#pragma unroll
                for (int ni = 0; ni < 4; ni++) {
                    const uint32_t* bh = &bhf[ni >> 1][(ni & 1) * 2];
                    MMA16816(c[mi][ni], af[mi], bh[0], bh[1]);
                }
            }
#pragma unroll
            for (int mi = 0; mi < 4; mi++) {
#pragma unroll
                for (int ni = 0; ni < 4; ni++) {
                    const uint32_t* bl = &blf[ni >> 1][(ni & 1) * 2];
                    MMA16816(c[mi][ni], af[mi], bl[0], bl[1]);
                }
            }
        }
        mbar_arrive(bempty[s]);
    }

    const int g   = lane >> 2;
    const int tig = lane & 3;
    const long m_base = (long)mb * 128 + wm * 64;
    const long n_base = (long)nb * 128 + wn * 32;
#pragma unroll
    for (int ni = 0; ni < 4; ni++) {
        const long col0 = n_base + ni * 8 + tig * 2;
        const float b0 = bias[col0], b1 = bias[col0 + 1];
#pragma unroll
        for (int mi = 0; mi < 4; mi++) {
            const long r0 = m_base + mi * 16 + g;
            float2 o0, o1;
            o0.x = scale * (c[mi][ni][0] + b0);
            o0.y = scale * (c[mi][ni][1] + b1);
            o1.x = scale * (c[mi][ni][2] + b0);
            o1.y = scale * (c[mi][ni][3] + b1);
            *reinterpret_cast<float2*>(C + r0 * D_MODEL + col0)       = o0;
            *reinterpret_cast<float2*>(C + (r0 + 8) * D_MODEL + col0) = o1;
        }
    }
}

// ---------------- attention over L=8 per n; emits fp16 ao into blocked A tiles ----------------
#define ROWP 1028
#define ATTN_SMEM ((3 * 8 * ROWP + 1024) * 4)   // 102784 bytes

__global__ void __launch_bounds__(256) attention_kernel(
    const float* __restrict__ q, const float* __restrict__ k,
    const float* __restrict__ v,
    char* __restrict__ ao, float* __restrict__ weights_out)
{
    extern __shared__ float sm[];
    float* qs  = sm;
    float* ks  = qs + 8 * ROWP;
    float* vs  = ks + 8 * ROWP;
    float* scr = vs + 8 * ROWP;        // [h][l][m] = 1024

    const int n = blockIdx.x;
    const int tid = threadIdx.x;

    for (int idx = tid; idx < 8 * 1024; idx += 256) {
        int l = idx >> 10, c = idx & 1023;
        size_t g = ((size_t)(l * SEQ + n)) * D_MODEL + c;
        qs[l * ROWP + c] = q[g];
        ks[l * ROWP + c] = k[g];
        vs[l * ROWP + c] = v[g];
    }
    __syncthreads();

    for (int t = tid; t < 1024; t += 256) {
        int h = t >> 6, l = (t >> 3) & 7, m = t & 7;
        const float* qp = qs + l * ROWP + h * HDIM;
        const float* kp = ks + m * ROWP + h * HDIM;
        float s = 0.f;
#pragma unroll
        for (int d = 0; d < HDIM; d++) s += qp[d] * kp[d];
        scr[t] = s;
    }
    __syncthreads();

    if (tid < 128) {
        float* rowp = scr + tid * 8;
        float mx = rowp[0];
#pragma unroll
        for (int m = 1; m < 8; m++) mx = fmaxf(mx, rowp[m]);
        float e[8], ssum = 0.f;
#pragma unroll
        for (int m = 0; m < 8; m++) { e[m] = __expf(rowp[m] - mx); ssum += e[m]; }
        float inv = 1.f / ssum;
#pragma unroll
        for (int m = 0; m < 8; m++) rowp[m] = e[m] * inv;
    }
    __syncthreads();

    if (weights_out != nullptr && tid < 64) {
        float s = 0.f;
#pragma unroll
        for (int h = 0; h < 16; h++) s += scr[h * 64 + tid];
        weights_out[(size_t)n * 64 + tid] = s * (1.f / 16.f);
    }

    const int nrow = n & 127;
    const int nblk = n >> 7;
    for (int t = tid; t < 8 * 512; t += 256) {
        int l  = t >> 9;
        int cp = (t & 511) * 2;
        int h  = cp >> 6;
        const float* a = scr + h * 64 + l * 8;
        float s0 = 0.f, s1 = 0.f;
#pragma unroll
        for (int m = 0; m < 8; m++) {
            float2 vv = *reinterpret_cast<const float2*>(vs + m * ROWP + cp);
            s0 += a[m] * vv.x;
            s1 += a[m] * vv.y;
        }

        int mb  = l * 32 + nblk;
        int kc  = cp >> 6;
        int col = cp & 63;
        uint32_t off = swz128((uint32_t)(nrow * 128 + col * 2));
        size_t tb = ((size_t)mb * 16 + kc) * 16384;
        *reinterpret_cast<uint32_t*>(ao + tb + off) = pack_h2(s0, s1);
    }
}

// ---------------- launch ----------------
extern "C" void kernel_launch(void* const* d_in, const int* in_sizes, int n_in,
                              void* d_out, int out_size)
{
    const float* query = (const float*)d_in[0];
    // d_in[1] = key : unused (reference aliasing bug — both pooled tensors are value)
    const float* value = (const float*)d_in[2];
    const float* in_w  = (const float*)d_in[3];
    const float* in_b  = (const float*)d_in[4];
    const float* out_w = (const float*)d_in[5];
    const float* out_b = (const float*)d_in[6];

    float* out = (float*)d_out;
    float* wts = ((size_t)out_size >= OUT_ELEMS + W_ELEMS) ? out + OUT_ELEMS : nullptr;

    float *q, *k, *v;
    __half *A, *Q, *Wh, *Wl;
    cudaGetSymbolAddress((void**)&q,  g_q);
    cudaGetSymbolAddress((void**)&k,  g_k);
    cudaGetSymbolAddress((void**)&v,  g_v);
    cudaGetSymbolAddress((void**)&A,  g_A);
    cudaGetSymbolAddress((void**)&Q,  g_Q);
    cudaGetSymbolAddress((void**)&Wh, g_Wh);
    cudaGetSymbolAddress((void**)&Wl, g_Wl);

    cudaFuncSetAttribute(gemm_mma_kernel,
                         cudaFuncAttributeMaxDynamicSharedMemorySize, GEMM_SMEM);
    cudaFuncSetAttribute(attention_kernel,
                         cudaFuncAttributeMaxDynamicSharedMemorySize, ATTN_SMEM);

    const size_t WS = 1024u * 1024u;   // elems per weight slot

    // --- weight split: slots 0,1,2 = Wq,Wk,Wv ; slot 3 = Wo ---
    convert_wsplit_kernel<<<(3072 * 128) / 256, 256>>>(in_w, (char*)Wh, (char*)Wl);
    convert_wsplit_kernel<<<(1024 * 128) / 256, 256>>>(out_w, (char*)(Wh + 3 * WS),
                                                       (char*)(Wl + 3 * WS));

    // --- activations (single fp16) ---
    window_mean_h_kernel<<<BATCH * 32, 512>>>(value, (char*)A);
    convert_h_kernel<<<(MROWS * 128) / 256, 256>>>(query, (char*)Q);

    dim3 gg(8, 256);
    // q = (query @ Wq^T + bq) / 8
    gemm_mma_kernel<<<gg, 256, GEMM_SMEM>>>(Q, Wh, Wl, in_b, q, 0.125f);
    // k = kv @ Wk^T + bk
    gemm_mma_kernel<<<gg, 256, GEMM_SMEM>>>(A, Wh + WS, Wl + WS,
                                            in_b + D_MODEL, k, 1.0f);
    // v = kv @ Wv^T + bv
    gemm_mma_kernel<<<gg, 256, GEMM_SMEM>>>(A, Wh + 2 * WS, Wl + 2 * WS,
                                            in_b + 2 * D_MODEL, v, 1.0f);

    // attention: ao = attn @ v -> fp16 blocked into Q (reused), + weights
    attention_kernel<<<SEQ, 256, ATTN_SMEM>>>(q, k, v, (char*)Q, wts);

    // out = ao @ Wo^T + bo -> d_out
    gemm_mma_kernel<<<gg, 256, GEMM_SMEM>>>(Q, Wh + 3 * WS, Wl + 3 * WS,
                                            out_b, out, 1.0f);
}

// round 9
// speedup vs baseline: 6.4135x; 1.4881x over previous
#include <cuda_runtime.h>
#include <cuda_fp16.h>
#include <cstdint>

// ---------------- problem constants ----------------
#define D_MODEL 1024
#define SEQ     4096
#define BATCH   8
#define HDIM    64
#define WIN     128
#define MROWS   (BATCH * SEQ)                          // 32768
#define OUT_ELEMS ((size_t)MROWS * D_MODEL)            // 33554432
#define W_ELEMS   ((size_t)SEQ * 64)                   // 262144

// ---------------- scratch (static device globals) ----------------
__device__ float g_q [OUT_ELEMS];
__device__ float g_k [OUT_ELEMS];
__device__ float g_v [OUT_ELEMS];
__device__ __half g_A [OUT_ELEMS];   // kv fp16, blocked
__device__ __half g_Q [OUT_ELEMS];   // query fp16, then ao fp16, blocked
__device__ __half g_W [4u * 1024u * 1024u];   // weight slots: 0=Wq 1=Wk 2=Wv 3=Wo

// ---------------- PTX helpers ----------------
__device__ __forceinline__ uint32_t smem_u32(const void* p) {
    uint32_t a;
    asm("{ .reg .u64 t; cvta.to.shared.u64 t, %1; cvt.u32.u64 %0, t; }" : "=r"(a) : "l"(p));
    return a;
}
__device__ __forceinline__ void mbar_init(uint32_t m, uint32_t cnt) {
    asm volatile("mbarrier.init.shared.b64 [%0], %1;" :: "r"(m), "r"(cnt) : "memory");
}
__device__ __forceinline__ void mbar_expect_tx(uint32_t m, uint32_t bytes) {
    asm volatile("mbarrier.arrive.expect_tx.shared.b64 _, [%0], %1;" :: "r"(m), "r"(bytes) : "memory");
}
__device__ __forceinline__ void mbar_arrive(uint32_t m) {
    asm volatile("mbarrier.arrive.shared.b64 _, [%0];" :: "r"(m) : "memory");
}
__device__ __forceinline__ void mbar_wait(uint32_t m, uint32_t parity) {
    asm volatile(
        "{\n\t.reg .pred P;\n\t"
        "WL_%=:\n\t"
        "mbarrier.try_wait.parity.acquire.cta.shared::cta.b64 P, [%0], %1, 0x989680;\n\t"
        "@P bra.uni WD_%=;\n\t"
        "bra.uni WL_%=;\n\t"
        "WD_%=:\n\t}"
        :: "r"(m), "r"(parity) : "memory");
}
__device__ __forceinline__ void bulk_g2s(uint32_t dst, const void* src, uint32_t bytes, uint32_t mbar) {
    asm volatile(
        "cp.async.bulk.shared::cluster.global.mbarrier::complete_tx::bytes [%0], [%1], %2, [%3];"
        :: "r"(dst), "l"(src), "r"(bytes), "r"(mbar) : "memory");
}

#define LDSM4(r, a) \
    asm volatile("ldmatrix.sync.aligned.m8n8.x4.shared.b16 {%0,%1,%2,%3}, [%4];" \
        : "=r"((r)[0]), "=r"((r)[1]), "=r"((r)[2]), "=r"((r)[3]) : "r"(a))

#define MMA16816(c, a, b0, b1) \
    asm volatile("mma.sync.aligned.m16n8k16.row.col.f32.f16.f16.f32 " \
        "{%0,%1,%2,%3}, {%4,%5,%6,%7}, {%8,%9}, {%0,%1,%2,%3};" \
        : "+f"((c)[0]), "+f"((c)[1]), "+f"((c)[2]), "+f"((c)[3]) \
        : "r"((a)[0]), "r"((a)[1]), "r"((a)[2]), "r"((a)[3]), "r"(b0), "r"(b1))

__host__ __device__ __forceinline__ uint32_t swz128(uint32_t o) { return o ^ ((o >> 3) & 0x70); }

__device__ __forceinline__ uint32_t pack_h2(float f0, float f1) {
    __half2 h = __floats2half2_rn(f0, f1);
    return *reinterpret_cast<uint32_t*>(&h);
}

// ---------------- window mean fused with fp16 convert ----------------
__global__ void __launch_bounds__(512) window_mean_h_kernel(
    const float* __restrict__ val, char* __restrict__ dst)
{
    int blk   = blockIdx.x;
    int chunk = blk & 31;
    int b     = blk >> 5;
    int d     = threadIdx.x * 2;

    const float2* base = reinterpret_cast<const float2*>(
        val + ((size_t)b * SEQ) * D_MODEL + d);

    int s0 = chunk * 128;
    int l  = max(s0 - WIN, 0);
    int r  = min(s0 + WIN + 1, SEQ);

    float sx = 0.f, sy = 0.f;
    for (int j = l; j < r; j++) {
        float2 t = base[(size_t)j * (D_MODEL / 2)];
        sx += t.x; sy += t.y;
    }

    const int kc  = d >> 6;
    const int col = d & 63;
    for (int s = s0; s < s0 + 128; s++) {
        if (s > s0) {
            int rn = s + WIN + 1;
            if (rn <= SEQ) {
                float2 t = base[(size_t)(rn - 1) * (D_MODEL / 2)];
                sx += t.x; sy += t.y; r = rn;
            }
            int ln = s - WIN;
            if (ln > 0) {
                float2 t = base[(size_t)(ln - 1) * (D_MODEL / 2)];
                sx -= t.x; sy -= t.y; l = ln;
            }
        }
        float inv = 1.f / (float)(r - l);

        int m   = b * SEQ + s;
        int mb  = m >> 7, row = m & 127;
        uint32_t off = swz128((uint32_t)(row * 128 + col * 2));
        size_t tb = ((size_t)mb * 16 + kc) * 16384;
        *reinterpret_cast<uint32_t*>(dst + tb + off) = pack_h2(sx * inv, sy * inv);
    }
}

// ---------------- fp32 -> fp16, 128-row tiles, pre-SW128-swizzled ----------------
__global__ void __launch_bounds__(256) convert_h_kernel(
    const float* __restrict__ x, char* __restrict__ dst)
{
    size_t idx = (size_t)blockIdx.x * 256 + threadIdx.x;   // one per 8 elements
    int m = (int)(idx >> 7);
    int k = (int)(idx & 127) << 3;

    const float4* p = reinterpret_cast<const float4*>(x + (size_t)m * 1024 + k);
    float4 f0 = p[0], f1 = p[1];

    uint4 o;
    o.x = pack_h2(f0.x, f0.y);
    o.y = pack_h2(f0.z, f0.w);
    o.z = pack_h2(f1.x, f1.y);
    o.w = pack_h2(f1.z, f1.w);

    int mb  = m >> 7;
    int row = m & 127;
    int kc  = k >> 6;
    int col = k & 63;
    uint32_t off = swz128((uint32_t)(row * 128 + col * 2));
    size_t tb = ((size_t)mb * 16 + kc) * 16384;
    *reinterpret_cast<uint4*>(dst + tb + off) = o;
}

// ---------------- mma.sync GEMM: C[m,n] = scale*(sum_k A[m,k]*W[n,k] + bias[n]) ----------------
// Single-term fp16 x fp16. A, W fp16 blocked/pre-swizzled. 4-stage bulk pipeline.
#define STAGE_BYTES 32768
#define NSTAGE 4
#define GEMM_SMEM (NSTAGE * STAGE_BYTES + 1024)

__global__ void __launch_bounds__(256, 1) gemm_mma_kernel(
    const __half* __restrict__ A, const __half* __restrict__ W,
    const float* __restrict__ bias, float* __restrict__ C, float scale)
{
    extern __shared__ char dsm[];
    __shared__ __align__(8) uint64_t bars[2 * NSTAGE];

    const int tid  = threadIdx.x;
    const int lane = tid & 31;
    const int w    = tid >> 5;
    const int wm   = w & 1;
    const int wn   = w >> 1;

    const uint32_t smraw = smem_u32(dsm);
    const uint32_t base  = (smraw + 1023u) & ~1023u;

    if (tid == 0) {
        for (int i = 0; i < NSTAGE; i++) {
            mbar_init(smem_u32(&bars[i]), 1);
            mbar_init(smem_u32(&bars[NSTAGE + i]), 256);
        }
        asm volatile("fence.proxy.async.shared::cta;" ::: "memory");
    }
    __syncthreads();

    uint32_t bfull[NSTAGE], bempty[NSTAGE];
#pragma unroll
    for (int i = 0; i < NSTAGE; i++) {
        bfull[i]  = smem_u32(&bars[i]);
        bempty[i] = smem_u32(&bars[NSTAGE + i]);
    }

    const int nb = blockIdx.x;
    const int mb = blockIdx.y;
    const char* ap = (const char*)A + (size_t)mb * 16 * 16384;
    const char* wp = (const char*)W + (size_t)nb * 16 * 16384;

    if (tid == 0) {
#pragma unroll
        for (int p = 0; p < 3; p++) {
            const uint32_t st = base + p * STAGE_BYTES;
            mbar_expect_tx(bfull[p], STAGE_BYTES);
            bulk_g2s(st,         ap + (size_t)p * 16384, 16384, bfull[p]);
            bulk_g2s(st + 16384, wp + (size_t)p * 16384, 16384, bfull[p]);
        }
    }

    const int r3 = lane & 7;
    const uint32_t xr = (uint32_t)(r3 << 4);
    const int arow = wm * 64 + r3 + ((lane >> 3) & 1) * 8;
    const uint32_t akh = (uint32_t)((lane >> 4) << 4);
    const int brow = wn * 32 + (lane >> 4) * 8 + r3;
    const uint32_t bkh = (uint32_t)(((lane >> 3) & 1) << 4);

    float c[4][4][4];
#pragma unroll
    for (int mi = 0; mi < 4; mi++)
#pragma unroll
        for (int ni = 0; ni < 4; ni++)
#pragma unroll
            for (int j = 0; j < 4; j++) c[mi][ni][j] = 0.f;

    for (int t = 0; t < 16; t++) {
        const int s = t % NSTAGE;
        if (tid == 0 && t + 3 < 16) {
            const int s2 = (t + 3) % NSTAGE;
            mbar_wait(bempty[s2], (uint32_t)((((t + 3) / NSTAGE) & 1) ^ 1));
            mbar_expect_tx(bfull[s2], STAGE_BYTES);
            const uint32_t st = base + s2 * STAGE_BYTES;
            bulk_g2s(st,         ap + (size_t)(t + 3) * 16384, 16384, bfull[s2]);
            bulk_g2s(st + 16384, wp + (size_t)(t + 3) * 16384, 16384, bfull[s2]);
        }
        mbar_wait(bfull[s], (uint32_t)((t / NSTAGE) & 1));

        const uint32_t st = base + s * STAGE_BYTES;
        const uint32_t tA = st, tW = st + 16384;

#pragma unroll
        for (int ks = 0; ks < 4; ks++) {
            const uint32_t offA = ((uint32_t)(ks * 32) + akh) ^ xr;
            const uint32_t offB = ((uint32_t)(ks * 32) + bkh) ^ xr;

            uint32_t af[4][4], bf[2][4];
#pragma unroll
            for (int mi = 0; mi < 4; mi++) {
                const uint32_t ra = (uint32_t)((arow + mi * 16) * 128);
                LDSM4(af[mi], tA + ra + offA);
            }
#pragma unroll
            for (int j = 0; j < 2; j++) {
                const uint32_t rb = (uint32_t)((brow + j * 16) * 128);
                LDSM4(bf[j], tW + rb + offB);
            }
#pragma unroll
            for (int mi = 0; mi < 4; mi++) {
#pragma unroll
                for (int ni = 0; ni < 4; ni++) {
                    const uint32_t* b = &bf[ni >> 1][(ni & 1) * 2];
                    MMA16816(c[mi][ni], af[mi], b[0], b[1]);
                }
            }
        }
        mbar_arrive(bempty[s]);
    }

    const int g   = lane >> 2;
    const int tig = lane & 3;
    const long m_base = (long)mb * 128 + wm * 64;
    const long n_base = (long)nb * 128 + wn * 32;
#pragma unroll
    for (int ni = 0; ni < 4; ni++) {
        const long col0 = n_base + ni * 8 + tig * 2;
        const float b0 = bias[col0], b1 = bias[col0 + 1];
#pragma unroll
        for (int mi = 0; mi < 4; mi++) {
            const long r0 = m_base + mi * 16 + g;
            float2 o0, o1;
            o0.x = scale * (c[mi][ni][0] + b0);
            o0.y = scale * (c[mi][ni][1] + b1);
            o1.x = scale * (c[mi][ni][2] + b0);
            o1.y = scale * (c[mi][ni][3] + b1);
            *reinterpret_cast<float2*>(C + r0 * D_MODEL + col0)       = o0;
            *reinterpret_cast<float2*>(C + (r0 + 8) * D_MODEL + col0) = o1;
        }
    }
}

// ---------------- attention over L=8 per n; emits fp16 ao into blocked A tiles ----------------
#define ROWP 1028
#define ATTN_SMEM ((3 * 8 * ROWP + 1024) * 4)   // 102784 bytes

__global__ void __launch_bounds__(256) attention_kernel(
    const float* __restrict__ q, const float* __restrict__ k,
    const float* __restrict__ v,
    char* __restrict__ ao, float* __restrict__ weights_out)
{
    extern __shared__ float sm[];
    float* qs  = sm;
    float* ks  = qs + 8 * ROWP;
    float* vs  = ks + 8 * ROWP;
    float* scr = vs + 8 * ROWP;        // [h][l][m] = 1024

    const int n = blockIdx.x;
    const int tid = threadIdx.x;

    for (int idx = tid; idx < 8 * 1024; idx += 256) {
        int l = idx >> 10, c = idx & 1023;
        size_t g = ((size_t)(l * SEQ + n)) * D_MODEL + c;
        qs[l * ROWP + c] = q[g];
        ks[l * ROWP + c] = k[g];
        vs[l * ROWP + c] = v[g];
    }
    __syncthreads();

    for (int t = tid; t < 1024; t += 256) {
        int h = t >> 6, l = (t >> 3) & 7, m = t & 7;
        const float* qp = qs + l * ROWP + h * HDIM;
        const float* kp = ks + m * ROWP + h * HDIM;
        float s = 0.f;
#pragma unroll
        for (int d = 0; d < HDIM; d++) s += qp[d] * kp[d];
        scr[t] = s;
    }
    __syncthreads();

    if (tid < 128) {
        float* rowp = scr + tid * 8;
        float mx = rowp[0];
#pragma unroll
        for (int m = 1; m < 8; m++) mx = fmaxf(mx, rowp[m]);
        float e[8], ssum = 0.f;
#pragma unroll
        for (int m = 0; m < 8; m++) { e[m] = __expf(rowp[m] - mx); ssum += e[m]; }
        float inv = 1.f / ssum;
#pragma unroll
        for (int m = 0; m < 8; m++) rowp[m] = e[m] * inv;
    }
    __syncthreads();

    if (weights_out != nullptr && tid < 64) {
        float s = 0.f;
#pragma unroll
        for (int h = 0; h < 16; h++) s += scr[h * 64 + tid];
        weights_out[(size_t)n * 64 + tid] = s * (1.f / 16.f);
    }

    const int nrow = n & 127;
    const int nblk = n >> 7;
    for (int t = tid; t < 8 * 512; t += 256) {
        int l  = t >> 9;
        int cp = (t & 511) * 2;
        int h  = cp >> 6;
        const float* a = scr + h * 64 + l * 8;
        float s0 = 0.f, s1 = 0.f;
#pragma unroll
        for (int m = 0; m < 8; m++) {
            float2 vv = *reinterpret_cast<const float2*>(vs + m * ROWP + cp);
            s0 += a[m] * vv.x;
            s1 += a[m] * vv.y;
        }

        int mb  = l * 32 + nblk;
        int kc  = cp >> 6;
        int col = cp & 63;
        uint32_t off = swz128((uint32_t)(nrow * 128 + col * 2));
        size_t tb = ((size_t)mb * 16 + kc) * 16384;
        *reinterpret_cast<uint32_t*>(ao + tb + off) = pack_h2(s0, s1);
    }
}

// ---------------- launch ----------------
extern "C" void kernel_launch(void* const* d_in, const int* in_sizes, int n_in,
                              void* d_out, int out_size)
{
    const float* query = (const float*)d_in[0];
    // d_in[1] = key : unused (reference aliasing bug — both pooled tensors are value)
    const float* value = (const float*)d_in[2];
    const float* in_w  = (const float*)d_in[3];
    const float* in_b  = (const float*)d_in[4];
    const float* out_w = (const float*)d_in[5];
    const float* out_b = (const float*)d_in[6];

    float* out = (float*)d_out;
    float* wts = ((size_t)out_size >= OUT_ELEMS + W_ELEMS) ? out + OUT_ELEMS : nullptr;

    float *q, *k, *v;
    __half *A, *Q, *W;
    cudaGetSymbolAddress((void**)&q,  g_q);
    cudaGetSymbolAddress((void**)&k,  g_k);
    cudaGetSymbolAddress((void**)&v,  g_v);
    cudaGetSymbolAddress((void**)&A,  g_A);
    cudaGetSymbolAddress((void**)&Q,  g_Q);
    cudaGetSymbolAddress((void**)&W,  g_W);

    cudaFuncSetAttribute(gemm_mma_kernel,
                         cudaFuncAttributeMaxDynamicSharedMemorySize, GEMM_SMEM);
    cudaFuncSetAttribute(attention_kernel,
                         cudaFuncAttributeMaxDynamicSharedMemorySize, ATTN_SMEM);

    const size_t WS = 1024u * 1024u;   // elems per weight slot

    // --- weights fp16, blocked: slots 0,1,2 = Wq,Wk,Wv ; slot 3 = Wo ---
    convert_h_kernel<<<(3072 * 128) / 256, 256>>>(in_w, (char*)W);
    convert_h_kernel<<<(1024 * 128) / 256, 256>>>(out_w, (char*)(W + 3 * WS));

    // --- activations fp16, blocked ---
    window_mean_h_kernel<<<BATCH * 32, 512>>>(value, (char*)A);
    convert_h_kernel<<<(MROWS * 128) / 256, 256>>>(query, (char*)Q);

    dim3 gg(8, 256);
    // q = (query @ Wq^T + bq) / 8
    gemm_mma_kernel<<<gg, 256, GEMM_SMEM>>>(Q, W, in_b, q, 0.125f);
    // k = kv @ Wk^T + bk
    gemm_mma_kernel<<<gg, 256, GEMM_SMEM>>>(A, W + WS, in_b + D_MODEL, k, 1.0f);
    // v = kv @ Wv^T + bv
    gemm_mma_kernel<<<gg, 256, GEMM_SMEM>>>(A, W + 2 * WS, in_b + 2 * D_MODEL, v, 1.0f);

    // attention: ao = attn @ v -> fp16 blocked into Q (reused), + weights
    attention_kernel<<<SEQ, 256, ATTN_SMEM>>>(q, k, v, (char*)Q, wts);

    // out = ao @ Wo^T + bo -> d_out
    gemm_mma_kernel<<<gg, 256, GEMM_SMEM>>>(Q, W + 3 * WS, out_b, out, 1.0f);
}